// round 13
// baseline (speedup 1.0000x reference)
#include <cuda_runtime.h>
#include <cuda_fp16.h>
#include <math.h>
#include <stdint.h>

// Problem constants
#define Bc   4
#define Nc   8192
#define Dc   512
#define Hc   8
#define DHc  64
#define Kc   64
#define HIDc 1024
#define Mrows (Bc*Nc)        // 32768
#define MH    (Mrows*Hc)     // 262144 token-heads
#define SEGc  16
#define SEGLEN (Nc/SEGc)     // 512

// Scratch (device globals; no allocation allowed)
__device__ float  g_stp [Bc*Hc*SEGc*Kc*DHc];
__device__ float  g_str [Bc*Hc*Kc*DHc];        // reduced st (unnormalized)
__device__ float  g_snp [Bc*Hc*SEGc*Kc];
__device__ float  g_snr [Bc*Hc*Kc];            // reduced snorm
__device__ float  g_o2  [(size_t)Mrows*Dc];
// fp16 operands
__device__ __half g_xh  [(size_t)Mrows*Dc];
__device__ __half g_xmh [(size_t)Mrows*Dc];
__device__ __half g_swh [(size_t)MH*Kc];
__device__ __half g_osth[Bc*Hc*Kc*DHc];
__device__ __half g_yh  [(size_t)Mrows*Dc];
__device__ __half g_lnh [(size_t)Mrows*Dc];
__device__ __half g_midh[(size_t)Mrows*HIDc];
// transposed fp16 weights [N][K]
#define BT_WX 0
#define BT_WP 262144
#define BT_W1 524288
#define BT_W2 1048576
__device__ __half g_bth [1572864];
__device__ __half g_tw1T[64*64];
__device__ __half g_wslT[64*64];

__device__ __forceinline__ float gelu_f(float x) {
    return 0.5f * x * (1.0f + erff(0.70710678118654752440f * x));
}
__device__ __forceinline__ unsigned s2u(const void* p) {
    return (unsigned)__cvta_generic_to_shared(p);
}
__device__ __forceinline__ void cpa16(void* s, const void* g) {
    unsigned sa = s2u(s);
    asm volatile("cp.async.cg.shared.global [%0], [%1], 16;\n" :: "r"(sa), "l"(g));
}
#define CP_COMMIT() asm volatile("cp.async.commit_group;\n")
#define CP_WAIT3()  asm volatile("cp.async.wait_group 3;\n")
#define CP_WAIT2()  asm volatile("cp.async.wait_group 2;\n")
#define CP_WAIT1()  asm volatile("cp.async.wait_group 1;\n")
#define CP_WAIT0()  asm volatile("cp.async.wait_group 0;\n")

__device__ __forceinline__ void mma_f16(float* c, const unsigned* a, const unsigned* b) {
    asm volatile(
        "mma.sync.aligned.m16n8k16.row.col.f32.f16.f16.f32 "
        "{%0,%1,%2,%3}, {%4,%5,%6,%7}, {%8,%9}, {%0,%1,%2,%3};\n"
        : "+f"(c[0]), "+f"(c[1]), "+f"(c[2]), "+f"(c[3])
        : "r"(a[0]), "r"(a[1]), "r"(a[2]), "r"(a[3]), "r"(b[0]), "r"(b[1]));
}
__device__ __forceinline__ void ldsm4(unsigned* r, const __half* p) {
    unsigned a = s2u(p);
    asm volatile("ldmatrix.sync.aligned.m8n8.x4.shared.b16 {%0,%1,%2,%3}, [%4];\n"
        : "=r"(r[0]), "=r"(r[1]), "=r"(r[2]), "=r"(r[3]) : "r"(a));
}
__device__ __forceinline__ void ldsm4t(unsigned* r, const __half* p) {
    unsigned a = s2u(p);
    asm volatile("ldmatrix.sync.aligned.m8n8.x4.trans.shared.b16 {%0,%1,%2,%3}, [%4];\n"
        : "=r"(r[0]), "=r"(r[1]), "=r"(r[2]), "=r"(r[3]) : "r"(a));
}
__device__ __forceinline__ void ldsmB(unsigned* r, const __half* tile, int n0,
                                      int stride, int kb, int lane) {
    int row = n0 + (lane & 7) + ((lane >> 4) << 3);
    int ko  = kb + (((lane >> 3) & 1) << 3);
    ldsm4(r, tile + row * stride + ko);
}
__device__ __forceinline__ void store2(float* C, size_t idx, float v0, float v1) {
    *(float2*)&C[idx] = make_float2(v0, v1);
}
__device__ __forceinline__ void store2(__half* C, size_t idx, float v0, float v1) {
    *(__half2*)&C[idx] = __floats2half2_rn(v0, v1);
}

// ---------------------------------------------------------------------------
// FP16 tensor-core GEMM — R9 shape, deepened to 4 stages.
// ---------------------------------------------------------------------------
#define BKh 32
#define HS  40
#define STAGEH (128*HS)
#define NSTh 4
#define GEMM_SMEM (NSTh*2*STAGEH*2)   // 81920 bytes

template<int EPI, typename OutT>
__global__ __launch_bounds__(256, 2) void gemm_h16(
    const __half* __restrict__ A, const __half* __restrict__ Bt,
    const float* __restrict__ bias, const float* __restrict__ res,
    OutT* __restrict__ C, int Kd, int Nd)
{
    extern __shared__ __half smh[];
    const int t = threadIdx.x;
    const int warp = t >> 5, lane = t & 31;
    const int g = lane >> 2, q = lane & 3;
    const int wm = (warp >> 2) << 6;
    const int wn = (warp & 3) << 5;
    const int m0 = blockIdx.y << 7;
    const int n0 = blockIdx.x << 7;
    const int lrow = lane & 15;
    const int lkof = (lane >> 4) << 3;
    const int r128 = t >> 1;
    const int hoff = (t & 1) << 4;
    const __half* Ap = A  + (size_t)(m0 + r128) * Kd + hoff;
    const __half* Bp = Bt + (size_t)(n0 + r128) * Kd + hoff;
    float acc[4][4][4] = {};

    auto load_tile = [&](int buf, int k0) {
        __half* As = smh + buf * 2 * STAGEH;
        __half* Bs = As + STAGEH;
        cpa16(As + r128 * HS + hoff,     Ap + k0);
        cpa16(As + r128 * HS + hoff + 8, Ap + k0 + 8);
        cpa16(Bs + r128 * HS + hoff,     Bp + k0);
        cpa16(Bs + r128 * HS + hoff + 8, Bp + k0 + 8);
        CP_COMMIT();
    };

    const int nk = Kd / BKh;   // 16 or 32 (>= NSTh)
    load_tile(0, 0);
    load_tile(1, BKh);
    load_tile(2, 2 * BKh);

    for (int it = 0; it < nk; ++it) {
        if (it + 3 < nk)       { load_tile((it + 3) % NSTh, (it + 3) * BKh); CP_WAIT3(); }
        else if (it + 3 == nk) { CP_WAIT2(); }
        else if (it + 2 == nk) { CP_WAIT1(); }
        else                   { CP_WAIT0(); }
        __syncthreads();
        const __half* As = smh + (it % NSTh) * 2 * STAGEH;
        const __half* Bs = As + STAGEH;
        #pragma unroll
        for (int ks = 0; ks < 2; ks++) {
            const int kb = ks << 4;
            unsigned af[4][4];
            #pragma unroll
            for (int mt = 0; mt < 4; mt++)
                ldsm4(af[mt], As + (wm + mt * 16 + lrow) * HS + kb + lkof);
            #pragma unroll
            for (int np = 0; np < 2; np++) {
                unsigned br[4];
                ldsmB(br, Bs, wn + np * 16, HS, kb, lane);
                #pragma unroll
                for (int mt = 0; mt < 4; mt++) {
                    mma_f16(acc[mt][2*np],     af[mt], br);
                    mma_f16(acc[mt][2*np + 1], af[mt], br + 2);
                }
            }
        }
        __syncthreads();
    }

    #pragma unroll
    for (int nt = 0; nt < 4; nt++) {
        const int col = n0 + wn + nt * 8 + (q << 1);
        const float b0 = bias[col], b1 = bias[col + 1];
        #pragma unroll
        for (int mt = 0; mt < 4; mt++) {
            int r0 = m0 + wm + mt * 16 + g;
            int r1 = r0 + 8;
            float v0 = acc[mt][nt][0] + b0, v1 = acc[mt][nt][1] + b1;
            float v2 = acc[mt][nt][2] + b0, v3 = acc[mt][nt][3] + b1;
            if (EPI == 2) { v0 = gelu_f(v0); v1 = gelu_f(v1); v2 = gelu_f(v2); v3 = gelu_f(v3); }
            if (EPI == 1) {
                const float2 ra = *(const float2*)&res[(size_t)r0 * Nd + col];
                const float2 rb = *(const float2*)&res[(size_t)r1 * Nd + col];
                v0 += ra.x; v1 += ra.y; v2 += rb.x; v3 += rb.y;
            }
            store2(C, (size_t)r0 * Nd + col, v0, v1);
            store2(C, (size_t)r1 * Nd + col, v2, v3);
        }
    }
}

// ---------------------------------------------------------------------------
// Fused prologue (unchanged)
// ---------------------------------------------------------------------------
__device__ __forceinline__ void transpose_blk(
    const float* __restrict__ S, __half* __restrict__ D,
    int R, int Ccol, int c0, int r0, int t)
{
    __shared__ float tl[32][33];
    int x = t & 31, y = t >> 5;
    #pragma unroll
    for (int j = 0; j < 32; j += 8)
        tl[y + j][x] = S[(size_t)(r0 + y + j) * Ccol + c0 + x];
    __syncthreads();
    #pragma unroll
    for (int j = 0; j < 32; j += 8)
        D[(size_t)(c0 + y + j) * R + r0 + x] = __float2half_rn(tl[x][y + j]);
}

#define PREP_CONV 8192
#define PREP_WX   (PREP_CONV)
#define PREP_WP   (PREP_WX + 256)
#define PREP_W1   (PREP_WP + 256)
#define PREP_W2   (PREP_W1 + 512)
#define PREP_TW1  (PREP_W2 + 512)
#define PREP_WSL  (PREP_TW1 + 4)
#define PREP_TOTAL (PREP_WSL + 4)

__global__ __launch_bounds__(256) void prep_k(
    const float* __restrict__ x,
    const float* __restrict__ Wx, const float* __restrict__ Wp,
    const float* __restrict__ W1, const float* __restrict__ W2,
    const float* __restrict__ tw1, const float* __restrict__ Wsl)
{
    const int id = blockIdx.x, t = threadIdx.x;
    if (id < PREP_CONV) {
        size_t i = ((size_t)id * 256 + t) * 8;
        float4 a = *(const float4*)&x[i];
        float4 b = *(const float4*)&x[i + 4];
        *(__half2*)&g_xh[i]     = __floats2half2_rn(a.x, a.y);
        *(__half2*)&g_xh[i + 2] = __floats2half2_rn(a.z, a.w);
        *(__half2*)&g_xh[i + 4] = __floats2half2_rn(b.x, b.y);
        *(__half2*)&g_xh[i + 6] = __floats2half2_rn(b.z, b.w);
    } else if (id < PREP_WP) {
        int i = id - PREP_WX;
        transpose_blk(Wx, g_bth + BT_WX, Dc, Dc, (i & 15) << 5, (i >> 4) << 5, t);
    } else if (id < PREP_W1) {
        int i = id - PREP_WP;
        transpose_blk(Wp, g_bth + BT_WP, Dc, Dc, (i & 15) << 5, (i >> 4) << 5, t);
    } else if (id < PREP_W2) {
        int i = id - PREP_W1;
        transpose_blk(W1, g_bth + BT_W1, Dc, HIDc, (i & 31) << 5, (i >> 5) << 5, t);
    } else if (id < PREP_TW1) {
        int i = id - PREP_W2;
        transpose_blk(W2, g_bth + BT_W2, HIDc, Dc, (i & 15) << 5, (i >> 4) << 5, t);
    } else if (id < PREP_WSL) {
        int i = id - PREP_TW1;
        transpose_blk(tw1, g_tw1T, 64, 64, (i & 1) << 5, (i >> 1) << 5, t);
    } else {
        int i = id - PREP_WSL;
        transpose_blk(Wsl, g_wslT, 64, 64, (i & 1) << 5, (i >> 1) << 5, t);
    }
}

// ---------------------------------------------------------------------------
// Router on tensor cores (unchanged from R12)
// ---------------------------------------------------------------------------
__global__ __launch_bounds__(256) void router_mma(
    const float* __restrict__ tb1, const float* __restrict__ tw2,
    const float* __restrict__ tb2, const float* __restrict__ bias,
    const float* __restrict__ bsl, const float* __restrict__ gumbel)
{
    __shared__ __half Xs[128*72];
    __shared__ __half W1s[64*72];
    __shared__ __half W2s[64*72];
    __shared__ float tb1s[64], tw2s[64], bsls[64];
    const int t = threadIdx.x, w = t >> 5, lane = t & 31;
    const int g = lane >> 2, q = lane & 3;
    const int m0 = blockIdx.x << 7;

    #pragma unroll
    for (int e = 0; e < 4; e++) {
        int sg = t + (e << 8);
        int r = sg >> 3, o = (sg & 7) << 3;
        cpa16(&Xs[r*72 + o], &g_xmh[(size_t)(m0 + r)*64 + o]);
    }
    #pragma unroll
    for (int e = 0; e < 2; e++) {
        int sg = t + (e << 8);
        int r = sg >> 3, o = (sg & 7) << 3;
        cpa16(&W1s[r*72 + o], &g_tw1T[r*64 + o]);
        cpa16(&W2s[r*72 + o], &g_wslT[r*64 + o]);
    }
    if (t < 64) { tb1s[t] = tb1[t]; tw2s[t] = tw2[t]; bsls[t] = bsl[t]; }
    CP_COMMIT(); CP_WAIT0();
    __syncthreads();

    unsigned af[4][4];
    #pragma unroll
    for (int ks = 0; ks < 4; ks++)
        ldsm4(af[ks], &Xs[(w*16 + (lane & 15))*72 + ks*16 + ((lane >> 4) << 3)]);

    float a1[8][4] = {}, a2[8][4] = {};
    #pragma unroll
    for (int nt = 0; nt < 8; nt++)
        #pragma unroll
        for (int ks = 0; ks < 4; ks++) {
            const __half* p1 = &W1s[(nt*8 + g)*72 + ks*16 + (q << 1)];
            const __half* p2 = &W2s[(nt*8 + g)*72 + ks*16 + (q << 1)];
            unsigned b1f[2] = {*(const unsigned*)p1, *(const unsigned*)(p1 + 8)};
            unsigned b2f[2] = {*(const unsigned*)p2, *(const unsigned*)(p2 + 8)};
            mma_f16(a1[nt], af[ks], b1f);
            mma_f16(a2[nt], af[ks], b2f);
        }

    const float tb2v = tb2[0];
    #pragma unroll
    for (int rr = 0; rr < 2; rr++) {
        const int m = m0 + w*16 + g + rr*8;
        const int h = m & 7;
        const int n = (m >> 3) & (Nc - 1);
        const int b = m >> 16;
        float p = 0.f;
        #pragma unroll
        for (int nt = 0; nt < 8; nt++) {
            int col = nt*8 + (q << 1);
            p += gelu_f(a1[nt][rr*2 + 0] + tb1s[col])     * tw2s[col];
            p += gelu_f(a1[nt][rr*2 + 1] + tb1s[col + 1]) * tw2s[col + 1];
        }
        p += __shfl_xor_sync(0xffffffffu, p, 1);
        p += __shfl_xor_sync(0xffffffffu, p, 2);
        const float invT = 1.0f / fmaxf(gelu_f(p + tb2v) + bias[h], 0.01f);

        const size_t gbase = (((size_t)b * Hc + h) * Nc + n) * 64;
        float z[8][2];
        float mx = -1e30f;
        #pragma unroll
        for (int nt = 0; nt < 8; nt++) {
            int col = nt*8 + (q << 1);
            float2 gu = *(const float2*)&gumbel[gbase + col];
            z[nt][0] = (a2[nt][rr*2 + 0] + bsls[col]     + gu.x) * invT;
            z[nt][1] = (a2[nt][rr*2 + 1] + bsls[col + 1] + gu.y) * invT;
            mx = fmaxf(mx, fmaxf(z[nt][0], z[nt][1]));
        }
        mx = fmaxf(mx, __shfl_xor_sync(0xffffffffu, mx, 1));
        mx = fmaxf(mx, __shfl_xor_sync(0xffffffffu, mx, 2));
        float sum = 0.f;
        #pragma unroll
        for (int nt = 0; nt < 8; nt++) {
            z[nt][0] = expf(z[nt][0] - mx);
            z[nt][1] = expf(z[nt][1] - mx);
            sum += z[nt][0] + z[nt][1];
        }
        sum += __shfl_xor_sync(0xffffffffu, sum, 1);
        sum += __shfl_xor_sync(0xffffffffu, sum, 2);
        const float inv = 1.0f / sum;
        #pragma unroll
        for (int nt = 0; nt < 8; nt++) {
            int col = nt*8 + (q << 1);
            *(__half2*)&g_swh[(size_t)m*64 + col] = __floats2half2_rn(z[nt][0]*inv, z[nt][1]*inv);
        }
    }
}

// ---------------------------------------------------------------------------
// Dispatch on tensor cores (unchanged from R12)
// ---------------------------------------------------------------------------
__global__ __launch_bounds__(256) void dispatch_mma()
{
    __shared__ __half swS[2][64*72];
    __shared__ __half xmS[2][64*72];
    const int t = threadIdx.x, w = t >> 5, lane = t & 31;
    const int g = lane >> 2, q = lane & 3;
    const int bh = blockIdx.x, s = blockIdx.y;
    const int b = bh >> 3, h = bh & 7;
    const int wm = (w & 3) << 4, wn = (w >> 2) << 5;
    const int lr = t >> 2;
    const int lo = (t & 3) << 4;
    const int trow = lane & 15;
    const int tcol = (lane >> 4) << 3;

    float acc[4][4] = {};
    float sn = 0.f;

    auto load_chunk = [&](int buf, int ch) {
        const int nb = s * SEGLEN + ch * 64;
        const size_t mrow = ((size_t)(b * Nc + nb + lr) * Hc + h) * 64;
        cpa16(&swS[buf][lr*72 + lo],     &g_swh[mrow + lo]);
        cpa16(&swS[buf][lr*72 + lo + 8], &g_swh[mrow + lo + 8]);
        cpa16(&xmS[buf][lr*72 + lo],     &g_xmh[mrow + lo]);
        cpa16(&xmS[buf][lr*72 + lo + 8], &g_xmh[mrow + lo + 8]);
        CP_COMMIT();
    };

    load_chunk(0, 0);
    load_chunk(1, 1);

    for (int ch = 0; ch < 8; ch++) {
        if (ch + 1 < 8) { CP_WAIT1(); } else { CP_WAIT0(); }
        __syncthreads();
        const int buf = ch & 1;
        const __half* swp = swS[buf];
        const __half* xmp = xmS[buf];

        if (t < 64) {
            float lsn = 0.f;
            #pragma unroll 8
            for (int tok = 0; tok < 64; tok++)
                lsn += __half2float(swp[tok*72 + t]);
            sn += lsn;
        }
        #pragma unroll
        for (int ks = 0; ks < 4; ks++) {
            const int tb = ks << 4;
            unsigned ar[4];
            ldsm4t(ar, &swp[(tb + trow)*72 + wm + tcol]);
            const unsigned af[4] = {ar[0], ar[2], ar[1], ar[3]};
            #pragma unroll
            for (int np = 0; np < 2; np++) {
                unsigned br[4];
                ldsm4t(br, &xmp[(tb + trow)*72 + wn + np*16 + tcol]);
                mma_f16(acc[np*2],     af, br);
                mma_f16(acc[np*2 + 1], af, br + 2);
            }
        }
        __syncthreads();
        if (ch + 2 < 8) load_chunk(buf, ch + 2);
    }

    const int base = bh * SEGc + s;
    #pragma unroll
    for (int nb = 0; nb < 4; nb++) {
        int col = wn + nb*8 + (q << 1);
        *(float2*)&g_stp[(size_t)base*4096 + (wm + g)*64 + col]     = make_float2(acc[nb][0], acc[nb][1]);
        *(float2*)&g_stp[(size_t)base*4096 + (wm + g + 8)*64 + col] = make_float2(acc[nb][2], acc[nb][3]);
    }
    if (t < 64) g_snp[base*64 + t] = sn;
}

// ---------------------------------------------------------------------------
// NEW: parallel reduce of g_stp/g_snp -> g_str/g_snr
// grid (32, 2), 256 threads; each thread reduces 8 st elements over 16 segs.
// ---------------------------------------------------------------------------
__global__ __launch_bounds__(256) void reduce_st()
{
    const int bh = blockIdx.x, part = blockIdx.y, t = threadIdx.x;
    const int idx = part * 2048 + t * 8;
    float v[8] = {};
    #pragma unroll
    for (int s = 0; s < SEGc; s++) {
        const float* p = &g_stp[(size_t)(bh * SEGc + s) * 4096 + idx];
        float4 a = *(const float4*)p;
        float4 b = *(const float4*)(p + 4);
        v[0] += a.x; v[1] += a.y; v[2] += a.z; v[3] += a.w;
        v[4] += b.x; v[5] += b.y; v[6] += b.z; v[7] += b.w;
    }
    float* o = &g_str[(size_t)bh * 4096 + idx];
    *(float4*)o       = make_float4(v[0], v[1], v[2], v[3]);
    *(float4*)(o + 4) = make_float4(v[4], v[5], v[6], v[7]);
    if (part == 0 && t < 64) {
        float sv = 0.f;
        #pragma unroll
        for (int s = 0; s < SEGc; s++) sv += g_snp[(bh * SEGc + s) * 64 + t];
        g_snr[bh * 64 + t] = sv;
    }
}

// ---------------------------------------------------------------------------
// Slice attention (reduce removed; reads g_str/g_snr)
// ---------------------------------------------------------------------------
#define SA_R 68
#define SA_SMEM ((1+3+3+1)*64*SA_R*4)

__global__ __launch_bounds__(256) void slice_attn(
    const float* __restrict__ Wq, const float* __restrict__ Wk, const float* __restrict__ Wv)
{
    extern __shared__ float sm[];
    float* STt = sm;
    float* Wsm = STt + 64 * SA_R;
    float* Qt  = Wsm + 3 * 64 * SA_R;
    float* Kt  = Qt + 64 * SA_R;
    float* Vs  = Kt + 64 * SA_R;
    float* Pt  = Vs + 64 * SA_R;
    __shared__ float invsn[64];

    const int bh = blockIdx.x, t = threadIdx.x;
    const int tx = t & 15, ty = t >> 4;
    const int r4 = ty << 2, c4 = tx << 2;

    if (t < 64) invsn[t] = 1.0f / (g_snr[bh * 64 + t] + 1e-5f);
    const float* Wg[3] = {Wq, Wk, Wv};
    #pragma unroll
    for (int m = 0; m < 3; m++)
        #pragma unroll
        for (int e = 0; e < 4; e++) {
            int idx = (t + (e << 8)) << 2;
            int r = idx >> 6, c = idx & 63;
            float4 wv4 = *(const float4*)&Wg[m][idx];
            *(float4*)&Wsm[(m * 64 + r) * SA_R + c] = wv4;
        }
    __syncthreads();

    #pragma unroll
    for (int e = 0; e < 16; e++) {
        int idx = t + (e << 8);
        float v = g_str[(size_t)bh * 4096 + idx];
        int tok = idx >> 6, d = idx & 63;
        STt[d * SA_R + tok] = v * invsn[tok];
    }
    __syncthreads();

    {
        float aq[4][4] = {}, ak[4][4] = {}, av[4][4] = {};
        #pragma unroll 4
        for (int d = 0; d < 64; d++) {
            float4 a4 = *(const float4*)&STt[d * SA_R + r4];
            float4 wq4 = *(const float4*)&Wsm[(0 * 64 + d) * SA_R + c4];
            float4 wk4 = *(const float4*)&Wsm[(1 * 64 + d) * SA_R + c4];
            float4 wv4 = *(const float4*)&Wsm[(2 * 64 + d) * SA_R + c4];
            const float a[4] = {a4.x, a4.y, a4.z, a4.w};
            const float uq[4] = {wq4.x, wq4.y, wq4.z, wq4.w};
            const float uk[4] = {wk4.x, wk4.y, wk4.z, wk4.w};
            const float uv[4] = {wv4.x, wv4.y, wv4.z, wv4.w};
            #pragma unroll
            for (int i = 0; i < 4; i++)
                #pragma unroll
                for (int j = 0; j < 4; j++) {
                    aq[i][j] += a[i] * uq[j];
                    ak[i][j] += a[i] * uk[j];
                    av[i][j] += a[i] * uv[j];
                }
        }
        __syncthreads();
        #pragma unroll
        for (int i = 0; i < 4; i++)
            #pragma unroll
            for (int j = 0; j < 4; j++) {
                Qt[(c4 + j) * SA_R + r4 + i] = aq[i][j];
                Kt[(c4 + j) * SA_R + r4 + i] = ak[i][j];
                Vs[(r4 + i) * SA_R + c4 + j] = av[i][j];
            }
    }
    __syncthreads();

    {
        float sc[4][4] = {};
        #pragma unroll 4
        for (int d = 0; d < 64; d++) {
            float4 a4 = *(const float4*)&Qt[d * SA_R + r4];
            float4 b4 = *(const float4*)&Kt[d * SA_R + c4];
            const float a[4] = {a4.x, a4.y, a4.z, a4.w};
            const float b[4] = {b4.x, b4.y, b4.z, b4.w};
            #pragma unroll
            for (int i = 0; i < 4; i++)
                #pragma unroll
                for (int j = 0; j < 4; j++) sc[i][j] += a[i] * b[j];
        }
        __syncthreads();
        #pragma unroll
        for (int i = 0; i < 4; i++)
            #pragma unroll
            for (int j = 0; j < 4; j++)
                Pt[(c4 + j) * SA_R + r4 + i] = sc[i][j] * 0.125f;
    }
    __syncthreads();

    if (t < 64) {
        float mx = -1e30f;
        #pragma unroll 8
        for (int j = 0; j < 64; j++) mx = fmaxf(mx, Pt[j * SA_R + t]);
        float sum = 0.f;
        #pragma unroll 8
        for (int j = 0; j < 64; j++) {
            float ee = expf(Pt[j * SA_R + t] - mx);
            Pt[j * SA_R + t] = ee;
            sum += ee;
        }
        float inv = 1.f / sum;
        #pragma unroll 8
        for (int j = 0; j < 64; j++) Pt[j * SA_R + t] *= inv;
    }
    __syncthreads();

    {
        float oc[4][4] = {};
        #pragma unroll 4
        for (int j = 0; j < 64; j++) {
            float4 a4 = *(const float4*)&Pt[j * SA_R + r4];
            float4 b4 = *(const float4*)&Vs[j * SA_R + c4];
            const float a[4] = {a4.x, a4.y, a4.z, a4.w};
            const float b[4] = {b4.x, b4.y, b4.z, b4.w};
            #pragma unroll
            for (int i = 0; i < 4; i++)
                #pragma unroll
                for (int jj = 0; jj < 4; jj++) oc[i][jj] += a[i] * b[jj];
        }
        #pragma unroll
        for (int i = 0; i < 4; i++)
            #pragma unroll
            for (int j = 0; j < 4; j++)
                g_osth[(size_t)bh * 4096 + (c4 + j) * 64 + (r4 + i)] = __float2half_rn(oc[i][j]);
    }
}

// ---------------------------------------------------------------------------
// Scatter on tensor cores (unchanged from R12)
// ---------------------------------------------------------------------------
__global__ __launch_bounds__(256) void scatter_mma()
{
    __shared__ __half As[128*72];
    __shared__ __half Bs[64*72];
    const int t = threadIdx.x, w = t >> 5, lane = t & 31;
    const int g = lane >> 2, q = lane & 3;
    const int tile = blockIdx.x;
    const int h = tile & 7, nt128 = (tile >> 3) & 63, b = tile >> 9;
    const int bh = b * 8 + h, n0 = nt128 << 7;

    #pragma unroll
    for (int e = 0; e < 2; e++) {
        int sg = t + (e << 8);
        int r = sg >> 3, o = (sg & 7) << 3;
        cpa16(&Bs[r*72 + o], &g_osth[(size_t)bh * 4096 + r*64 + o]);
    }
    #pragma unroll
    for (int e = 0; e < 4; e++) {
        int sg = t + (e << 8);
        int r = sg >> 3, o = (sg & 7) << 3;
        cpa16(&As[r*72 + o], &g_swh[((size_t)(b * Nc + n0 + r) * Hc + h) * 64 + o]);
    }
    CP_COMMIT(); CP_WAIT0();
    __syncthreads();

    unsigned af[4][4];
    #pragma unroll
    for (int ks = 0; ks < 4; ks++)
        ldsm4(af[ks], &As[(w*16 + (lane & 15))*72 + ks*16 + ((lane >> 4) << 3)]);
    float acc[8][4] = {};
    #pragma unroll
    for (int nt = 0; nt < 8; nt++)
        #pragma unroll
        for (int ks = 0; ks < 4; ks++) {
            const __half* bp = &Bs[(nt*8 + g)*72 + ks*16 + (q << 1)];
            unsigned bf[2] = {*(const unsigned*)bp, *(const unsigned*)(bp + 8)};
            mma_f16(acc[nt], af[ks], bf);
        }
    #pragma unroll
    for (int nt = 0; nt < 8; nt++) {
        int col = nt*8 + (q << 1);
        int r0 = n0 + w*16 + g;
        *(__half2*)&g_yh[(size_t)(b * Nc + r0) * Dc + h*64 + col] =
            __floats2half2_rn(acc[nt][0], acc[nt][1]);
        *(__half2*)&g_yh[(size_t)(b * Nc + r0 + 8) * Dc + h*64 + col] =
            __floats2half2_rn(acc[nt][2], acc[nt][3]);
    }
}

// ---------------------------------------------------------------------------
__global__ __launch_bounds__(128) void ln_k(
    const float* __restrict__ gam, const float* __restrict__ bet)
{
    int row = blockIdx.x, t = threadIdx.x;
    const float4 v = *(const float4*)&g_o2[(size_t)row * Dc + (t << 2)];
    float s = v.x + v.y + v.z + v.w;
    __shared__ float rs[4];
    #pragma unroll
    for (int off = 16; off; off >>= 1) s += __shfl_xor_sync(0xffffffffu, s, off);
    int w = t >> 5;
    if ((t & 31) == 0) rs[w] = s;
    __syncthreads();
    float mean = (rs[0] + rs[1] + rs[2] + rs[3]) * (1.f / 512.f);
    float dx = v.x - mean, dy = v.y - mean, dz = v.z - mean, dw = v.w - mean;
    float qv = dx*dx + dy*dy + dz*dz + dw*dw;
    #pragma unroll
    for (int off = 16; off; off >>= 1) qv += __shfl_xor_sync(0xffffffffu, qv, off);
    __syncthreads();
    if ((t & 31) == 0) rs[w] = qv;
    __syncthreads();
    float var = (rs[0] + rs[1] + rs[2] + rs[3]) * (1.f / 512.f);
    float inv = rsqrtf(var + 1e-5f);
    float4 gv = *(const float4*)&gam[t << 2];
    float4 bv = *(const float4*)&bet[t << 2];
    size_t base = (size_t)row * Dc + (t << 2);
    *(__half2*)&g_lnh[base]     = __floats2half2_rn(dx * inv * gv.x + bv.x, dy * inv * gv.y + bv.y);
    *(__half2*)&g_lnh[base + 2] = __floats2half2_rn(dz * inv * gv.z + bv.z, dw * inv * gv.w + bv.w);
}

// ---------------------------------------------------------------------------
extern "C" void kernel_launch(void* const* d_in, const int* in_sizes, int n_in,
                              void* d_out, int out_size)
{
    const float* x      = (const float*)d_in[0];
    const float* gumbel = (const float*)d_in[1];
    const float* Wx     = (const float*)d_in[2];
    const float* bx     = (const float*)d_in[3];
    const float* tw1    = (const float*)d_in[4];
    const float* tb1    = (const float*)d_in[5];
    const float* tw2    = (const float*)d_in[6];
    const float* tb2    = (const float*)d_in[7];
    const float* bias   = (const float*)d_in[8];
    const float* Wsl    = (const float*)d_in[9];
    const float* bsl    = (const float*)d_in[10];
    const float* Wq     = (const float*)d_in[11];
    const float* Wk     = (const float*)d_in[12];
    const float* Wv     = (const float*)d_in[13];
    const float* Wp     = (const float*)d_in[14];
    const float* bp     = (const float*)d_in[15];
    const float* ln2g   = (const float*)d_in[16];
    const float* ln2b   = (const float*)d_in[17];
    const float* W1     = (const float*)d_in[18];
    const float* b1     = (const float*)d_in[19];
    const float* W2     = (const float*)d_in[20];
    const float* b2     = (const float*)d_in[21];
    float* out = (float*)d_out;

    float *o2;
    __half *xh, *xmh, *yh, *lnh, *midh, *bth;
    cudaGetSymbolAddress((void**)&o2,   g_o2);
    cudaGetSymbolAddress((void**)&xh,   g_xh);
    cudaGetSymbolAddress((void**)&xmh,  g_xmh);
    cudaGetSymbolAddress((void**)&yh,   g_yh);
    cudaGetSymbolAddress((void**)&lnh,  g_lnh);
    cudaGetSymbolAddress((void**)&midh, g_midh);
    cudaGetSymbolAddress((void**)&bth,  g_bth);

    cudaFuncSetAttribute((const void*)gemm_h16<0,__half>, cudaFuncAttributeMaxDynamicSharedMemorySize, GEMM_SMEM);
    cudaFuncSetAttribute((const void*)gemm_h16<1,float>,  cudaFuncAttributeMaxDynamicSharedMemorySize, GEMM_SMEM);
    cudaFuncSetAttribute((const void*)gemm_h16<2,__half>, cudaFuncAttributeMaxDynamicSharedMemorySize, GEMM_SMEM);
    cudaFuncSetAttribute((const void*)slice_attn,         cudaFuncAttributeMaxDynamicSharedMemorySize, SA_SMEM);

    // 0. fused prologue
    prep_k<<<PREP_TOTAL, 256>>>(x, Wx, Wp, W1, W2, tw1, Wsl);

    // 1. xm = x @ Wx + bx  (fp16 out)
    gemm_h16<0,__half><<<dim3(Dc/128, Mrows/128), 256, GEMM_SMEM>>>(xh, bth + BT_WX, bx, nullptr, xmh, Dc, Dc);
    // 2. router -> g_swh
    router_mma<<<MH/128, 256>>>(tb1, tw2, tb2, bias, bsl, gumbel);
    // 3. dispatch
    dispatch_mma<<<dim3(Bc*Hc, SEGc), 256>>>();
    // 3b. parallel reduce of partials
    reduce_st<<<dim3(Bc*Hc, 2), 256>>>();
    // 4. slice attention -> g_osth
    slice_attn<<<Bc*Hc, 256, SA_SMEM>>>(Wq, Wk, Wv);
    // 5. scatter -> g_yh
    scatter_mma<<<Bc*Hc*64, 256>>>();
    // 6. o2 = y @ Wp + bp + x
    gemm_h16<1,float><<<dim3(Dc/128, Mrows/128), 256, GEMM_SMEM>>>(yh, bth + BT_WP, bp, x, o2, Dc, Dc);
    // 7. layernorm (fp16 out)
    ln_k<<<Mrows, 128>>>(ln2g, ln2b);
    // 8. mid = gelu(ln @ W1 + b1)  (fp16 out)
    gemm_h16<2,__half><<<dim3(HIDc/128, Mrows/128), 256, GEMM_SMEM>>>(lnh, bth + BT_W1, b1, nullptr, midh, Dc, HIDc);
    // 9. out = mid @ W2 + b2 + x
    gemm_h16<1,float><<<dim3(Dc/128, Mrows/128), 256, GEMM_SMEM>>>(midh, bth + BT_W2, b2, x, out, HIDc, Dc);
}

// round 14
// speedup vs baseline: 1.0091x; 1.0091x over previous
#include <cuda_runtime.h>
#include <cuda_fp16.h>
#include <math.h>
#include <stdint.h>

// Problem constants
#define Bc   4
#define Nc   8192
#define Dc   512
#define Hc   8
#define DHc  64
#define Kc   64
#define HIDc 1024
#define Mrows (Bc*Nc)        // 32768
#define MH    (Mrows*Hc)     // 262144 token-heads
#define SEGc  32
#define SEGLEN (Nc/SEGc)     // 256

// Scratch (device globals; no allocation allowed)
__device__ float  g_stp [Bc*Hc*SEGc*Kc*DHc];   // 16MB
__device__ float  g_str [Bc*Hc*Kc*DHc];
__device__ float  g_snp [Bc*Hc*SEGc*Kc];
__device__ float  g_snr [Bc*Hc*Kc];
__device__ float  g_o2  [(size_t)Mrows*Dc];
// fp16 operands
__device__ __half g_xh  [(size_t)Mrows*Dc];
__device__ __half g_xmh [(size_t)Mrows*Dc];
__device__ __half g_swh [(size_t)MH*Kc];
__device__ __half g_osth[Bc*Hc*Kc*DHc];
__device__ __half g_yh  [(size_t)Mrows*Dc];
__device__ __half g_lnh [(size_t)Mrows*Dc];
__device__ __half g_midh[(size_t)Mrows*HIDc];
// transposed fp16 weights [N][K]
#define BT_WX 0
#define BT_WP 262144
#define BT_W1 524288
#define BT_W2 1048576
__device__ __half g_bth [1572864];
__device__ __half g_tw1T[64*64];
__device__ __half g_wslT[64*64];

__device__ __forceinline__ float gelu_f(float x) {
    return 0.5f * x * (1.0f + erff(0.70710678118654752440f * x));
}
__device__ __forceinline__ unsigned s2u(const void* p) {
    return (unsigned)__cvta_generic_to_shared(p);
}
__device__ __forceinline__ void cpa16(void* s, const void* g) {
    unsigned sa = s2u(s);
    asm volatile("cp.async.cg.shared.global [%0], [%1], 16;\n" :: "r"(sa), "l"(g));
}
#define CP_COMMIT() asm volatile("cp.async.commit_group;\n")
#define CP_WAIT2()  asm volatile("cp.async.wait_group 2;\n")
#define CP_WAIT1()  asm volatile("cp.async.wait_group 1;\n")
#define CP_WAIT0()  asm volatile("cp.async.wait_group 0;\n")

__device__ __forceinline__ void mma_f16(float* c, const unsigned* a, const unsigned* b) {
    asm volatile(
        "mma.sync.aligned.m16n8k16.row.col.f32.f16.f16.f32 "
        "{%0,%1,%2,%3}, {%4,%5,%6,%7}, {%8,%9}, {%0,%1,%2,%3};\n"
        : "+f"(c[0]), "+f"(c[1]), "+f"(c[2]), "+f"(c[3])
        : "r"(a[0]), "r"(a[1]), "r"(a[2]), "r"(a[3]), "r"(b[0]), "r"(b[1]));
}
__device__ __forceinline__ void ldsm4(unsigned* r, const __half* p) {
    unsigned a = s2u(p);
    asm volatile("ldmatrix.sync.aligned.m8n8.x4.shared.b16 {%0,%1,%2,%3}, [%4];\n"
        : "=r"(r[0]), "=r"(r[1]), "=r"(r[2]), "=r"(r[3]) : "r"(a));
}
__device__ __forceinline__ void ldsm4t(unsigned* r, const __half* p) {
    unsigned a = s2u(p);
    asm volatile("ldmatrix.sync.aligned.m8n8.x4.trans.shared.b16 {%0,%1,%2,%3}, [%4];\n"
        : "=r"(r[0]), "=r"(r[1]), "=r"(r[2]), "=r"(r[3]) : "r"(a));
}
__device__ __forceinline__ void ldsmB(unsigned* r, const __half* tile, int n0,
                                      int stride, int kb, int lane) {
    int row = n0 + (lane & 7) + ((lane >> 4) << 3);
    int ko  = kb + (((lane >> 3) & 1) << 3);
    ldsm4(r, tile + row * stride + ko);
}
__device__ __forceinline__ void store2(float* C, size_t idx, float v0, float v1) {
    *(float2*)&C[idx] = make_float2(v0, v1);
}
__device__ __forceinline__ void store2(__half* C, size_t idx, float v0, float v1) {
    *(__half2*)&C[idx] = __floats2half2_rn(v0, v1);
}

// ---------------------------------------------------------------------------
// FP16 tensor-core GEMM — exact R12 form (BK=32, 3-stage, ldsmB).
// ---------------------------------------------------------------------------
#define BKh 32
#define HS  40
#define STAGEH (128*HS)
#define NSTh 3
#define GEMM_SMEM (NSTh*2*STAGEH*2)

template<int EPI, typename OutT>
__global__ __launch_bounds__(256, 2) void gemm_h16(
    const __half* __restrict__ A, const __half* __restrict__ Bt,
    const float* __restrict__ bias, const float* __restrict__ res,
    OutT* __restrict__ C, int Kd, int Nd)
{
    extern __shared__ __half smh[];
    const int t = threadIdx.x;
    const int warp = t >> 5, lane = t & 31;
    const int g = lane >> 2, q = lane & 3;
    const int wm = (warp >> 2) << 6;
    const int wn = (warp & 3) << 5;
    const int m0 = blockIdx.y << 7;
    const int n0 = blockIdx.x << 7;
    const int lrow = lane & 15;
    const int lkof = (lane >> 4) << 3;
    const int r128 = t >> 1;
    const int hoff = (t & 1) << 4;
    const __half* Ap = A  + (size_t)(m0 + r128) * Kd + hoff;
    const __half* Bp = Bt + (size_t)(n0 + r128) * Kd + hoff;
    float acc[4][4][4] = {};

    auto load_tile = [&](int buf, int k0) {
        __half* As = smh + buf * 2 * STAGEH;
        __half* Bs = As + STAGEH;
        cpa16(As + r128 * HS + hoff,     Ap + k0);
        cpa16(As + r128 * HS + hoff + 8, Ap + k0 + 8);
        cpa16(Bs + r128 * HS + hoff,     Bp + k0);
        cpa16(Bs + r128 * HS + hoff + 8, Bp + k0 + 8);
        CP_COMMIT();
    };

    const int nk = Kd / BKh;
    load_tile(0, 0);
    load_tile(1, BKh);

    for (int it = 0; it < nk; ++it) {
        if (it + 2 < nk)       { load_tile((it + 2) % NSTh, (it + 2) * BKh); CP_WAIT2(); }
        else if (it + 2 == nk) { CP_WAIT1(); }
        else                   { CP_WAIT0(); }
        __syncthreads();
        const __half* As = smh + (it % NSTh) * 2 * STAGEH;
        const __half* Bs = As + STAGEH;
        #pragma unroll
        for (int ks = 0; ks < 2; ks++) {
            const int kb = ks << 4;
            unsigned af[4][4];
            #pragma unroll
            for (int mt = 0; mt < 4; mt++)
                ldsm4(af[mt], As + (wm + mt * 16 + lrow) * HS + kb + lkof);
            #pragma unroll
            for (int np = 0; np < 2; np++) {
                unsigned br[4];
                ldsmB(br, Bs, wn + np * 16, HS, kb, lane);
                #pragma unroll
                for (int mt = 0; mt < 4; mt++) {
                    mma_f16(acc[mt][2*np],     af[mt], br);
                    mma_f16(acc[mt][2*np + 1], af[mt], br + 2);
                }
            }
        }
        __syncthreads();
    }

    #pragma unroll
    for (int nt = 0; nt < 4; nt++) {
        const int col = n0 + wn + nt * 8 + (q << 1);
        const float b0 = bias[col], b1 = bias[col + 1];
        #pragma unroll
        for (int mt = 0; mt < 4; mt++) {
            int r0 = m0 + wm + mt * 16 + g;
            int r1 = r0 + 8;
            float v0 = acc[mt][nt][0] + b0, v1 = acc[mt][nt][1] + b1;
            float v2 = acc[mt][nt][2] + b0, v3 = acc[mt][nt][3] + b1;
            if (EPI == 2) { v0 = gelu_f(v0); v1 = gelu_f(v1); v2 = gelu_f(v2); v3 = gelu_f(v3); }
            if (EPI == 1) {
                const float2 ra = *(const float2*)&res[(size_t)r0 * Nd + col];
                const float2 rb = *(const float2*)&res[(size_t)r1 * Nd + col];
                v0 += ra.x; v1 += ra.y; v2 += rb.x; v3 += rb.y;
            }
            store2(C, (size_t)r0 * Nd + col, v0, v1);
            store2(C, (size_t)r1 * Nd + col, v2, v3);
        }
    }
}

// ---------------------------------------------------------------------------
// Fused prologue (unchanged)
// ---------------------------------------------------------------------------
__device__ __forceinline__ void transpose_blk(
    const float* __restrict__ S, __half* __restrict__ D,
    int R, int Ccol, int c0, int r0, int t)
{
    __shared__ float tl[32][33];
    int x = t & 31, y = t >> 5;
    #pragma unroll
    for (int j = 0; j < 32; j += 8)
        tl[y + j][x] = S[(size_t)(r0 + y + j) * Ccol + c0 + x];
    __syncthreads();
    #pragma unroll
    for (int j = 0; j < 32; j += 8)
        D[(size_t)(c0 + y + j) * R + r0 + x] = __float2half_rn(tl[x][y + j]);
}

#define PREP_CONV 8192
#define PREP_WX   (PREP_CONV)
#define PREP_WP   (PREP_WX + 256)
#define PREP_W1   (PREP_WP + 256)
#define PREP_W2   (PREP_W1 + 512)
#define PREP_TW1  (PREP_W2 + 512)
#define PREP_WSL  (PREP_TW1 + 4)
#define PREP_TOTAL (PREP_WSL + 4)

__global__ __launch_bounds__(256) void prep_k(
    const float* __restrict__ x,
    const float* __restrict__ Wx, const float* __restrict__ Wp,
    const float* __restrict__ W1, const float* __restrict__ W2,
    const float* __restrict__ tw1, const float* __restrict__ Wsl)
{
    const int id = blockIdx.x, t = threadIdx.x;
    if (id < PREP_CONV) {
        size_t i = ((size_t)id * 256 + t) * 8;
        float4 a = *(const float4*)&x[i];
        float4 b = *(const float4*)&x[i + 4];
        *(__half2*)&g_xh[i]     = __floats2half2_rn(a.x, a.y);
        *(__half2*)&g_xh[i + 2] = __floats2half2_rn(a.z, a.w);
        *(__half2*)&g_xh[i + 4] = __floats2half2_rn(b.x, b.y);
        *(__half2*)&g_xh[i + 6] = __floats2half2_rn(b.z, b.w);
    } else if (id < PREP_WP) {
        int i = id - PREP_WX;
        transpose_blk(Wx, g_bth + BT_WX, Dc, Dc, (i & 15) << 5, (i >> 4) << 5, t);
    } else if (id < PREP_W1) {
        int i = id - PREP_WP;
        transpose_blk(Wp, g_bth + BT_WP, Dc, Dc, (i & 15) << 5, (i >> 4) << 5, t);
    } else if (id < PREP_W2) {
        int i = id - PREP_W1;
        transpose_blk(W1, g_bth + BT_W1, Dc, HIDc, (i & 31) << 5, (i >> 5) << 5, t);
    } else if (id < PREP_TW1) {
        int i = id - PREP_W2;
        transpose_blk(W2, g_bth + BT_W2, HIDc, Dc, (i & 15) << 5, (i >> 4) << 5, t);
    } else if (id < PREP_WSL) {
        int i = id - PREP_TW1;
        transpose_blk(tw1, g_tw1T, 64, 64, (i & 1) << 5, (i >> 1) << 5, t);
    } else {
        int i = id - PREP_WSL;
        transpose_blk(Wsl, g_wslT, 64, 64, (i & 1) << 5, (i >> 1) << 5, t);
    }
}

// ---------------------------------------------------------------------------
// Router on tensor cores (unchanged)
// ---------------------------------------------------------------------------
__global__ __launch_bounds__(256) void router_mma(
    const float* __restrict__ tb1, const float* __restrict__ tw2,
    const float* __restrict__ tb2, const float* __restrict__ bias,
    const float* __restrict__ bsl, const float* __restrict__ gumbel)
{
    __shared__ __half Xs[128*72];
    __shared__ __half W1s[64*72];
    __shared__ __half W2s[64*72];
    __shared__ float tb1s[64], tw2s[64], bsls[64];
    const int t = threadIdx.x, w = t >> 5, lane = t & 31;
    const int g = lane >> 2, q = lane & 3;
    const int m0 = blockIdx.x << 7;

    #pragma unroll
    for (int e = 0; e < 4; e++) {
        int sg = t + (e << 8);
        int r = sg >> 3, o = (sg & 7) << 3;
        cpa16(&Xs[r*72 + o], &g_xmh[(size_t)(m0 + r)*64 + o]);
    }
    #pragma unroll
    for (int e = 0; e < 2; e++) {
        int sg = t + (e << 8);
        int r = sg >> 3, o = (sg & 7) << 3;
        cpa16(&W1s[r*72 + o], &g_tw1T[r*64 + o]);
        cpa16(&W2s[r*72 + o], &g_wslT[r*64 + o]);
    }
    if (t < 64) { tb1s[t] = tb1[t]; tw2s[t] = tw2[t]; bsls[t] = bsl[t]; }
    CP_COMMIT(); CP_WAIT0();
    __syncthreads();

    unsigned af[4][4];
    #pragma unroll
    for (int ks = 0; ks < 4; ks++)
        ldsm4(af[ks], &Xs[(w*16 + (lane & 15))*72 + ks*16 + ((lane >> 4) << 3)]);

    float a1[8][4] = {}, a2[8][4] = {};
    #pragma unroll
    for (int nt = 0; nt < 8; nt++)
        #pragma unroll
        for (int ks = 0; ks < 4; ks++) {
            const __half* p1 = &W1s[(nt*8 + g)*72 + ks*16 + (q << 1)];
            const __half* p2 = &W2s[(nt*8 + g)*72 + ks*16 + (q << 1)];
            unsigned b1f[2] = {*(const unsigned*)p1, *(const unsigned*)(p1 + 8)};
            unsigned b2f[2] = {*(const unsigned*)p2, *(const unsigned*)(p2 + 8)};
            mma_f16(a1[nt], af[ks], b1f);
            mma_f16(a2[nt], af[ks], b2f);
        }

    const float tb2v = tb2[0];
    #pragma unroll
    for (int rr = 0; rr < 2; rr++) {
        const int m = m0 + w*16 + g + rr*8;
        const int h = m & 7;
        const int n = (m >> 3) & (Nc - 1);
        const int b = m >> 16;
        float p = 0.f;
        #pragma unroll
        for (int nt = 0; nt < 8; nt++) {
            int col = nt*8 + (q << 1);
            p += gelu_f(a1[nt][rr*2 + 0] + tb1s[col])     * tw2s[col];
            p += gelu_f(a1[nt][rr*2 + 1] + tb1s[col + 1]) * tw2s[col + 1];
        }
        p += __shfl_xor_sync(0xffffffffu, p, 1);
        p += __shfl_xor_sync(0xffffffffu, p, 2);
        const float invT = 1.0f / fmaxf(gelu_f(p + tb2v) + bias[h], 0.01f);

        const size_t gbase = (((size_t)b * Hc + h) * Nc + n) * 64;
        float z[8][2];
        float mx = -1e30f;
        #pragma unroll
        for (int nt = 0; nt < 8; nt++) {
            int col = nt*8 + (q << 1);
            float2 gu = *(const float2*)&gumbel[gbase + col];
            z[nt][0] = (a2[nt][rr*2 + 0] + bsls[col]     + gu.x) * invT;
            z[nt][1] = (a2[nt][rr*2 + 1] + bsls[col + 1] + gu.y) * invT;
            mx = fmaxf(mx, fmaxf(z[nt][0], z[nt][1]));
        }
        mx = fmaxf(mx, __shfl_xor_sync(0xffffffffu, mx, 1));
        mx = fmaxf(mx, __shfl_xor_sync(0xffffffffu, mx, 2));
        float sum = 0.f;
        #pragma unroll
        for (int nt = 0; nt < 8; nt++) {
            z[nt][0] = expf(z[nt][0] - mx);
            z[nt][1] = expf(z[nt][1] - mx);
            sum += z[nt][0] + z[nt][1];
        }
        sum += __shfl_xor_sync(0xffffffffu, sum, 1);
        sum += __shfl_xor_sync(0xffffffffu, sum, 2);
        const float inv = 1.0f / sum;
        #pragma unroll
        for (int nt = 0; nt < 8; nt++) {
            int col = nt*8 + (q << 1);
            *(__half2*)&g_swh[(size_t)m*64 + col] = __floats2half2_rn(z[nt][0]*inv, z[nt][1]*inv);
        }
    }
}

// ---------------------------------------------------------------------------
// Dispatch on tensor cores (SEGc=32: 4 chunks of 64 tokens per block)
// ---------------------------------------------------------------------------
__global__ __launch_bounds__(256) void dispatch_mma()
{
    __shared__ __half swS[2][64*72];
    __shared__ __half xmS[2][64*72];
    const int t = threadIdx.x, w = t >> 5, lane = t & 31;
    const int g = lane >> 2, q = lane & 3;
    const int bh = blockIdx.x, s = blockIdx.y;
    const int b = bh >> 3, h = bh & 7;
    const int wm = (w & 3) << 4, wn = (w >> 2) << 5;
    const int lr = t >> 2;
    const int lo = (t & 3) << 4;
    const int trow = lane & 15;
    const int tcol = (lane >> 4) << 3;
    const int NCH = SEGLEN / 64;   // 4

    float acc[4][4] = {};
    float sn = 0.f;

    auto load_chunk = [&](int buf, int ch) {
        const int nb = s * SEGLEN + ch * 64;
        const size_t mrow = ((size_t)(b * Nc + nb + lr) * Hc + h) * 64;
        cpa16(&swS[buf][lr*72 + lo],     &g_swh[mrow + lo]);
        cpa16(&swS[buf][lr*72 + lo + 8], &g_swh[mrow + lo + 8]);
        cpa16(&xmS[buf][lr*72 + lo],     &g_xmh[mrow + lo]);
        cpa16(&xmS[buf][lr*72 + lo + 8], &g_xmh[mrow + lo + 8]);
        CP_COMMIT();
    };

    load_chunk(0, 0);
    load_chunk(1, 1);

    for (int ch = 0; ch < NCH; ch++) {
        if (ch + 1 < NCH) { CP_WAIT1(); } else { CP_WAIT0(); }
        __syncthreads();
        const int buf = ch & 1;
        const __half* swp = swS[buf];
        const __half* xmp = xmS[buf];

        if (t < 64) {
            float lsn = 0.f;
            #pragma unroll 8
            for (int tok = 0; tok < 64; tok++)
                lsn += __half2float(swp[tok*72 + t]);
            sn += lsn;
        }
        #pragma unroll
        for (int ks = 0; ks < 4; ks++) {
            const int tb = ks << 4;
            unsigned ar[4];
            ldsm4t(ar, &swp[(tb + trow)*72 + wm + tcol]);
            const unsigned af[4] = {ar[0], ar[2], ar[1], ar[3]};
            #pragma unroll
            for (int np = 0; np < 2; np++) {
                unsigned br[4];
                ldsm4t(br, &xmp[(tb + trow)*72 + wn + np*16 + tcol]);
                mma_f16(acc[np*2],     af, br);
                mma_f16(acc[np*2 + 1], af, br + 2);
            }
        }
        __syncthreads();
        if (ch + 2 < NCH) load_chunk(buf, ch + 2);
    }

    const int base = bh * SEGc + s;
    #pragma unroll
    for (int nb = 0; nb < 4; nb++) {
        int col = wn + nb*8 + (q << 1);
        *(float2*)&g_stp[(size_t)base*4096 + (wm + g)*64 + col]     = make_float2(acc[nb][0], acc[nb][1]);
        *(float2*)&g_stp[(size_t)base*4096 + (wm + g + 8)*64 + col] = make_float2(acc[nb][2], acc[nb][3]);
    }
    if (t < 64) g_snp[base*64 + t] = sn;
}

// ---------------------------------------------------------------------------
// Parallel reduce of partials -> g_str/g_snr
// ---------------------------------------------------------------------------
__global__ __launch_bounds__(256) void reduce_st()
{
    const int bh = blockIdx.x, part = blockIdx.y, t = threadIdx.x;
    const int idx = part * 2048 + t * 8;
    float v[8] = {};
    #pragma unroll
    for (int s = 0; s < SEGc; s++) {
        const float* p = &g_stp[(size_t)(bh * SEGc + s) * 4096 + idx];
        float4 a = *(const float4*)p;
        float4 b = *(const float4*)(p + 4);
        v[0] += a.x; v[1] += a.y; v[2] += a.z; v[3] += a.w;
        v[4] += b.x; v[5] += b.y; v[6] += b.z; v[7] += b.w;
    }
    float* o = &g_str[(size_t)bh * 4096 + idx];
    *(float4*)o       = make_float4(v[0], v[1], v[2], v[3]);
    *(float4*)(o + 4) = make_float4(v[4], v[5], v[6], v[7]);
    if (part == 0 && t < 64) {
        float sv = 0.f;
        #pragma unroll
        for (int s = 0; s < SEGc; s++) sv += g_snp[(bh * SEGc + s) * 64 + t];
        g_snr[bh * 64 + t] = sv;
    }
}

// ---------------------------------------------------------------------------
// Slice attention (reads g_str/g_snr)
// ---------------------------------------------------------------------------
#define SA_R 68
#define SA_SMEM ((1+3+3+1)*64*SA_R*4)

__global__ __launch_bounds__(256) void slice_attn(
    const float* __restrict__ Wq, const float* __restrict__ Wk, const float* __restrict__ Wv)
{
    extern __shared__ float sm[];
    float* STt = sm;
    float* Wsm = STt + 64 * SA_R;
    float* Qt  = Wsm + 3 * 64 * SA_R;
    float* Kt  = Qt + 64 * SA_R;
    float* Vs  = Kt + 64 * SA_R;
    float* Pt  = Vs + 64 * SA_R;
    __shared__ float invsn[64];

    const int bh = blockIdx.x, t = threadIdx.x;
    const int tx = t & 15, ty = t >> 4;
    const int r4 = ty << 2, c4 = tx << 2;

    if (t < 64) invsn[t] = 1.0f / (g_snr[bh * 64 + t] + 1e-5f);
    const float* Wg[3] = {Wq, Wk, Wv};
    #pragma unroll
    for (int m = 0; m < 3; m++)
        #pragma unroll
        for (int e = 0; e < 4; e++) {
            int idx = (t + (e << 8)) << 2;
            int r = idx >> 6, c = idx & 63;
            float4 wv4 = *(const float4*)&Wg[m][idx];
            *(float4*)&Wsm[(m * 64 + r) * SA_R + c] = wv4;
        }
    __syncthreads();

    #pragma unroll
    for (int e = 0; e < 16; e++) {
        int idx = t + (e << 8);
        float v = g_str[(size_t)bh * 4096 + idx];
        int tok = idx >> 6, d = idx & 63;
        STt[d * SA_R + tok] = v * invsn[tok];
    }
    __syncthreads();

    {
        float aq[4][4] = {}, ak[4][4] = {}, av[4][4] = {};
        #pragma unroll 4
        for (int d = 0; d < 64; d++) {
            float4 a4 = *(const float4*)&STt[d * SA_R + r4];
            float4 wq4 = *(const float4*)&Wsm[(0 * 64 + d) * SA_R + c4];
            float4 wk4 = *(const float4*)&Wsm[(1 * 64 + d) * SA_R + c4];
            float4 wv4 = *(const float4*)&Wsm[(2 * 64 + d) * SA_R + c4];
            const float a[4] = {a4.x, a4.y, a4.z, a4.w};
            const float uq[4] = {wq4.x, wq4.y, wq4.z, wq4.w};
            const float uk[4] = {wk4.x, wk4.y, wk4.z, wk4.w};
            const float uv[4] = {wv4.x, wv4.y, wv4.z, wv4.w};
            #pragma unroll
            for (int i = 0; i < 4; i++)
                #pragma unroll
                for (int j = 0; j < 4; j++) {
                    aq[i][j] += a[i] * uq[j];
                    ak[i][j] += a[i] * uk[j];
                    av[i][j] += a[i] * uv[j];
                }
        }
        __syncthreads();
        #pragma unroll
        for (int i = 0; i < 4; i++)
            #pragma unroll
            for (int j = 0; j < 4; j++) {
                Qt[(c4 + j) * SA_R + r4 + i] = aq[i][j];
                Kt[(c4 + j) * SA_R + r4 + i] = ak[i][j];
                Vs[(r4 + i) * SA_R + c4 + j] = av[i][j];
            }
    }
    __syncthreads();

    {
        float sc[4][4] = {};
        #pragma unroll 4
        for (int d = 0; d < 64; d++) {
            float4 a4 = *(const float4*)&Qt[d * SA_R + r4];
            float4 b4 = *(const float4*)&Kt[d * SA_R + c4];
            const float a[4] = {a4.x, a4.y, a4.z, a4.w};
            const float b[4] = {b4.x, b4.y, b4.z, b4.w};
            #pragma unroll
            for (int i = 0; i < 4; i++)
                #pragma unroll
                for (int j = 0; j < 4; j++) sc[i][j] += a[i] * b[j];
        }
        __syncthreads();
        #pragma unroll
        for (int i = 0; i < 4; i++)
            #pragma unroll
            for (int j = 0; j < 4; j++)
                Pt[(c4 + j) * SA_R + r4 + i] = sc[i][j] * 0.125f;
    }
    __syncthreads();

    if (t < 64) {
        float mx = -1e30f;
        #pragma unroll 8
        for (int j = 0; j < 64; j++) mx = fmaxf(mx, Pt[j * SA_R + t]);
        float sum = 0.f;
        #pragma unroll 8
        for (int j = 0; j < 64; j++) {
            float ee = expf(Pt[j * SA_R + t] - mx);
            Pt[j * SA_R + t] = ee;
            sum += ee;
        }
        float inv = 1.f / sum;
        #pragma unroll 8
        for (int j = 0; j < 64; j++) Pt[j * SA_R + t] *= inv;
    }
    __syncthreads();

    {
        float oc[4][4] = {};
        #pragma unroll 4
        for (int j = 0; j < 64; j++) {
            float4 a4 = *(const float4*)&Pt[j * SA_R + r4];
            float4 b4 = *(const float4*)&Vs[j * SA_R + c4];
            const float a[4] = {a4.x, a4.y, a4.z, a4.w};
            const float b[4] = {b4.x, b4.y, b4.z, b4.w};
            #pragma unroll
            for (int i = 0; i < 4; i++)
                #pragma unroll
                for (int jj = 0; jj < 4; jj++) oc[i][jj] += a[i] * b[jj];
        }
        #pragma unroll
        for (int i = 0; i < 4; i++)
            #pragma unroll
            for (int j = 0; j < 4; j++)
                g_osth[(size_t)bh * 4096 + (c4 + j) * 64 + (r4 + i)] = __float2half_rn(oc[i][j]);
    }
}

// ---------------------------------------------------------------------------
// Scatter on tensor cores (unchanged)
// ---------------------------------------------------------------------------
__global__ __launch_bounds__(256) void scatter_mma()
{
    __shared__ __half As[128*72];
    __shared__ __half Bs[64*72];
    const int t = threadIdx.x, w = t >> 5, lane = t & 31;
    const int g = lane >> 2, q = lane & 3;
    const int tile = blockIdx.x;
    const int h = tile & 7, nt128 = (tile >> 3) & 63, b = tile >> 9;
    const int bh = b * 8 + h, n0 = nt128 << 7;

    #pragma unroll
    for (int e = 0; e < 2; e++) {
        int sg = t + (e << 8);
        int r = sg >> 3, o = (sg & 7) << 3;
        cpa16(&Bs[r*72 + o], &g_osth[(size_t)bh * 4096 + r*64 + o]);
    }
    #pragma unroll
    for (int e = 0; e < 4; e++) {
        int sg = t + (e << 8);
        int r = sg >> 3, o = (sg & 7) << 3;
        cpa16(&As[r*72 + o], &g_swh[((size_t)(b * Nc + n0 + r) * Hc + h) * 64 + o]);
    }
    CP_COMMIT(); CP_WAIT0();
    __syncthreads();

    unsigned af[4][4];
    #pragma unroll
    for (int ks = 0; ks < 4; ks++)
        ldsm4(af[ks], &As[(w*16 + (lane & 15))*72 + ks*16 + ((lane >> 4) << 3)]);
    float acc[8][4] = {};
    #pragma unroll
    for (int nt = 0; nt < 8; nt++)
        #pragma unroll
        for (int ks = 0; ks < 4; ks++) {
            const __half* bp = &Bs[(nt*8 + g)*72 + ks*16 + (q << 1)];
            unsigned bf[2] = {*(const unsigned*)bp, *(const unsigned*)(bp + 8)};
            mma_f16(acc[nt], af[ks], bf);
        }
    #pragma unroll
    for (int nt = 0; nt < 8; nt++) {
        int col = nt*8 + (q << 1);
        int r0 = n0 + w*16 + g;
        *(__half2*)&g_yh[(size_t)(b * Nc + r0) * Dc + h*64 + col] =
            __floats2half2_rn(acc[nt][0], acc[nt][1]);
        *(__half2*)&g_yh[(size_t)(b * Nc + r0 + 8) * Dc + h*64 + col] =
            __floats2half2_rn(acc[nt][2], acc[nt][3]);
    }
}

// ---------------------------------------------------------------------------
__global__ __launch_bounds__(128) void ln_k(
    const float* __restrict__ gam, const float* __restrict__ bet)
{
    int row = blockIdx.x, t = threadIdx.x;
    const float4 v = *(const float4*)&g_o2[(size_t)row * Dc + (t << 2)];
    float s = v.x + v.y + v.z + v.w;
    __shared__ float rs[4];
    #pragma unroll
    for (int off = 16; off; off >>= 1) s += __shfl_xor_sync(0xffffffffu, s, off);
    int w = t >> 5;
    if ((t & 31) == 0) rs[w] = s;
    __syncthreads();
    float mean = (rs[0] + rs[1] + rs[2] + rs[3]) * (1.f / 512.f);
    float dx = v.x - mean, dy = v.y - mean, dz = v.z - mean, dw = v.w - mean;
    float qv = dx*dx + dy*dy + dz*dz + dw*dw;
    #pragma unroll
    for (int off = 16; off; off >>= 1) qv += __shfl_xor_sync(0xffffffffu, qv, off);
    __syncthreads();
    if ((t & 31) == 0) rs[w] = qv;
    __syncthreads();
    float var = (rs[0] + rs[1] + rs[2] + rs[3]) * (1.f / 512.f);
    float inv = rsqrtf(var + 1e-5f);
    float4 gv = *(const float4*)&gam[t << 2];
    float4 bv = *(const float4*)&bet[t << 2];
    size_t base = (size_t)row * Dc + (t << 2);
    *(__half2*)&g_lnh[base]     = __floats2half2_rn(dx * inv * gv.x + bv.x, dy * inv * gv.y + bv.y);
    *(__half2*)&g_lnh[base + 2] = __floats2half2_rn(dz * inv * gv.z + bv.z, dw * inv * gv.w + bv.w);
}

// ---------------------------------------------------------------------------
extern "C" void kernel_launch(void* const* d_in, const int* in_sizes, int n_in,
                              void* d_out, int out_size)
{
    const float* x      = (const float*)d_in[0];
    const float* gumbel = (const float*)d_in[1];
    const float* Wx     = (const float*)d_in[2];
    const float* bx     = (const float*)d_in[3];
    const float* tw1    = (const float*)d_in[4];
    const float* tb1    = (const float*)d_in[5];
    const float* tw2    = (const float*)d_in[6];
    const float* tb2    = (const float*)d_in[7];
    const float* bias   = (const float*)d_in[8];
    const float* Wsl    = (const float*)d_in[9];
    const float* bsl    = (const float*)d_in[10];
    const float* Wq     = (const float*)d_in[11];
    const float* Wk     = (const float*)d_in[12];
    const float* Wv     = (const float*)d_in[13];
    const float* Wp     = (const float*)d_in[14];
    const float* bp     = (const float*)d_in[15];
    const float* ln2g   = (const float*)d_in[16];
    const float* ln2b   = (const float*)d_in[17];
    const float* W1     = (const float*)d_in[18];
    const float* b1     = (const float*)d_in[19];
    const float* W2     = (const float*)d_in[20];
    const float* b2     = (const float*)d_in[21];
    float* out = (float*)d_out;

    float *o2;
    __half *xh, *xmh, *yh, *lnh, *midh, *bth;
    cudaGetSymbolAddress((void**)&o2,   g_o2);
    cudaGetSymbolAddress((void**)&xh,   g_xh);
    cudaGetSymbolAddress((void**)&xmh,  g_xmh);
    cudaGetSymbolAddress((void**)&yh,   g_yh);
    cudaGetSymbolAddress((void**)&lnh,  g_lnh);
    cudaGetSymbolAddress((void**)&midh, g_midh);
    cudaGetSymbolAddress((void**)&bth,  g_bth);

    cudaFuncSetAttribute((const void*)gemm_h16<0,__half>, cudaFuncAttributeMaxDynamicSharedMemorySize, GEMM_SMEM);
    cudaFuncSetAttribute((const void*)gemm_h16<1,float>,  cudaFuncAttributeMaxDynamicSharedMemorySize, GEMM_SMEM);
    cudaFuncSetAttribute((const void*)gemm_h16<2,__half>, cudaFuncAttributeMaxDynamicSharedMemorySize, GEMM_SMEM);
    cudaFuncSetAttribute((const void*)slice_attn,         cudaFuncAttributeMaxDynamicSharedMemorySize, SA_SMEM);

    // 0. fused prologue
    prep_k<<<PREP_TOTAL, 256>>>(x, Wx, Wp, W1, W2, tw1, Wsl);

    // 1. xm = x @ Wx + bx  (fp16 out)
    gemm_h16<0,__half><<<dim3(Dc/128, Mrows/128), 256, GEMM_SMEM>>>(xh, bth + BT_WX, bx, nullptr, xmh, Dc, Dc);
    // 2. router -> g_swh
    router_mma<<<MH/128, 256>>>(tb1, tw2, tb2, bias, bsl, gumbel);
    // 3. dispatch (SEGc=32 -> grid 1024)
    dispatch_mma<<<dim3(Bc*Hc, SEGc), 256>>>();
    // 3b. parallel reduce of partials
    reduce_st<<<dim3(Bc*Hc, 2), 256>>>();
    // 4. slice attention -> g_osth
    slice_attn<<<Bc*Hc, 256, SA_SMEM>>>(Wq, Wk, Wv);
    // 5. scatter -> g_yh
    scatter_mma<<<Bc*Hc*64, 256>>>();
    // 6. o2 = y @ Wp + bp + x
    gemm_h16<1,float><<<dim3(Dc/128, Mrows/128), 256, GEMM_SMEM>>>(yh, bth + BT_WP, bp, x, o2, Dc, Dc);
    // 7. layernorm (fp16 out)
    ln_k<<<Mrows, 128>>>(ln2g, ln2b);
    // 8. mid = gelu(ln @ W1 + b1)  (fp16 out)
    gemm_h16<2,__half><<<dim3(HIDc/128, Mrows/128), 256, GEMM_SMEM>>>(lnh, bth + BT_W1, b1, nullptr, midh, Dc, HIDc);
    // 9. out = mid @ W2 + b2 + x
    gemm_h16<1,float><<<dim3(Dc/128, Mrows/128), 256, GEMM_SMEM>>>(midh, bth + BT_W2, b2, x, out, HIDc, Dc);
}

// round 15
// speedup vs baseline: 1.0210x; 1.0118x over previous
#include <cuda_runtime.h>
#include <cuda_fp16.h>
#include <math.h>
#include <stdint.h>

// Problem constants
#define Bc   4
#define Nc   8192
#define Dc   512
#define Hc   8
#define DHc  64
#define Kc   64
#define HIDc 1024
#define Mrows (Bc*Nc)        // 32768
#define MH    (Mrows*Hc)     // 262144 token-heads
#define SEGc  16
#define SEGLEN (Nc/SEGc)     // 512

// Scratch (device globals; no allocation allowed)
__device__ float  g_stp [Bc*Hc*SEGc*Kc*DHc];
__device__ float  g_snp [Bc*Hc*SEGc*Kc];
// fp16 operands
__device__ __half g_o2h [(size_t)Mrows*Dc];     // o2 (LN input) fp16
__device__ __half g_xh  [(size_t)Mrows*Dc];
__device__ __half g_xmh [(size_t)Mrows*Dc];
__device__ __half g_swh [(size_t)MH*Kc];
__device__ __half g_osth[Bc*Hc*Kc*DHc];
__device__ __half g_yh  [(size_t)Mrows*Dc];
__device__ __half g_lnh [(size_t)Mrows*Dc];
__device__ __half g_midh[(size_t)Mrows*HIDc];
// transposed fp16 weights [N][K]
#define BT_WX 0
#define BT_WP 262144
#define BT_W1 524288
#define BT_W2 1048576
__device__ __half g_bth [1572864];
__device__ __half g_tw1T[64*64];
__device__ __half g_wslT[64*64];

__device__ __forceinline__ float gelu_f(float x) {
    return 0.5f * x * (1.0f + erff(0.70710678118654752440f * x));
}
__device__ __forceinline__ unsigned s2u(const void* p) {
    return (unsigned)__cvta_generic_to_shared(p);
}
__device__ __forceinline__ void cpa16(void* s, const void* g) {
    unsigned sa = s2u(s);
    asm volatile("cp.async.cg.shared.global [%0], [%1], 16;\n" :: "r"(sa), "l"(g));
}
#define CP_COMMIT() asm volatile("cp.async.commit_group;\n")
#define CP_WAIT2()  asm volatile("cp.async.wait_group 2;\n")
#define CP_WAIT1()  asm volatile("cp.async.wait_group 1;\n")
#define CP_WAIT0()  asm volatile("cp.async.wait_group 0;\n")

__device__ __forceinline__ void mma_f16(float* c, const unsigned* a, const unsigned* b) {
    asm volatile(
        "mma.sync.aligned.m16n8k16.row.col.f32.f16.f16.f32 "
        "{%0,%1,%2,%3}, {%4,%5,%6,%7}, {%8,%9}, {%0,%1,%2,%3};\n"
        : "+f"(c[0]), "+f"(c[1]), "+f"(c[2]), "+f"(c[3])
        : "r"(a[0]), "r"(a[1]), "r"(a[2]), "r"(a[3]), "r"(b[0]), "r"(b[1]));
}
__device__ __forceinline__ void ldsm4(unsigned* r, const __half* p) {
    unsigned a = s2u(p);
    asm volatile("ldmatrix.sync.aligned.m8n8.x4.shared.b16 {%0,%1,%2,%3}, [%4];\n"
        : "=r"(r[0]), "=r"(r[1]), "=r"(r[2]), "=r"(r[3]) : "r"(a));
}
__device__ __forceinline__ void ldsm4t(unsigned* r, const __half* p) {
    unsigned a = s2u(p);
    asm volatile("ldmatrix.sync.aligned.m8n8.x4.trans.shared.b16 {%0,%1,%2,%3}, [%4];\n"
        : "=r"(r[0]), "=r"(r[1]), "=r"(r[2]), "=r"(r[3]) : "r"(a));
}
__device__ __forceinline__ void ldsmB(unsigned* r, const __half* tile, int n0,
                                      int stride, int kb, int lane) {
    int row = n0 + (lane & 7) + ((lane >> 4) << 3);
    int ko  = kb + (((lane >> 3) & 1) << 3);
    ldsm4(r, tile + row * stride + ko);
}
__device__ __forceinline__ void store2(float* C, size_t idx, float v0, float v1) {
    *(float2*)&C[idx] = make_float2(v0, v1);
}
__device__ __forceinline__ void store2(__half* C, size_t idx, float v0, float v1) {
    *(__half2*)&C[idx] = __floats2half2_rn(v0, v1);
}

// ---------------------------------------------------------------------------
// FP16 tensor-core GEMM — exact R12 form (BK=32, 3-stage, ldsmB).
// ---------------------------------------------------------------------------
#define BKh 32
#define HS  40
#define STAGEH (128*HS)
#define NSTh 3
#define GEMM_SMEM (NSTh*2*STAGEH*2)

template<int EPI, typename OutT>
__global__ __launch_bounds__(256, 2) void gemm_h16(
    const __half* __restrict__ A, const __half* __restrict__ Bt,
    const float* __restrict__ bias, const float* __restrict__ res,
    OutT* __restrict__ C, int Kd, int Nd)
{
    extern __shared__ __half smh[];
    const int t = threadIdx.x;
    const int warp = t >> 5, lane = t & 31;
    const int g = lane >> 2, q = lane & 3;
    const int wm = (warp >> 2) << 6;
    const int wn = (warp & 3) << 5;
    const int m0 = blockIdx.y << 7;
    const int n0 = blockIdx.x << 7;
    const int lrow = lane & 15;
    const int lkof = (lane >> 4) << 3;
    const int r128 = t >> 1;
    const int hoff = (t & 1) << 4;
    const __half* Ap = A  + (size_t)(m0 + r128) * Kd + hoff;
    const __half* Bp = Bt + (size_t)(n0 + r128) * Kd + hoff;
    float acc[4][4][4] = {};

    auto load_tile = [&](int buf, int k0) {
        __half* As = smh + buf * 2 * STAGEH;
        __half* Bs = As + STAGEH;
        cpa16(As + r128 * HS + hoff,     Ap + k0);
        cpa16(As + r128 * HS + hoff + 8, Ap + k0 + 8);
        cpa16(Bs + r128 * HS + hoff,     Bp + k0);
        cpa16(Bs + r128 * HS + hoff + 8, Bp + k0 + 8);
        CP_COMMIT();
    };

    const int nk = Kd / BKh;
    load_tile(0, 0);
    load_tile(1, BKh);

    for (int it = 0; it < nk; ++it) {
        if (it + 2 < nk)       { load_tile((it + 2) % NSTh, (it + 2) * BKh); CP_WAIT2(); }
        else if (it + 2 == nk) { CP_WAIT1(); }
        else                   { CP_WAIT0(); }
        __syncthreads();
        const __half* As = smh + (it % NSTh) * 2 * STAGEH;
        const __half* Bs = As + STAGEH;
        #pragma unroll
        for (int ks = 0; ks < 2; ks++) {
            const int kb = ks << 4;
            unsigned af[4][4];
            #pragma unroll
            for (int mt = 0; mt < 4; mt++)
                ldsm4(af[mt], As + (wm + mt * 16 + lrow) * HS + kb + lkof);
            #pragma unroll
            for (int np = 0; np < 2; np++) {
                unsigned br[4];
                ldsmB(br, Bs, wn + np * 16, HS, kb, lane);
                #pragma unroll
                for (int mt = 0; mt < 4; mt++) {
                    mma_f16(acc[mt][2*np],     af[mt], br);
                    mma_f16(acc[mt][2*np + 1], af[mt], br + 2);
                }
            }
        }
        __syncthreads();
    }

    #pragma unroll
    for (int nt = 0; nt < 4; nt++) {
        const int col = n0 + wn + nt * 8 + (q << 1);
        const float b0 = bias[col], b1 = bias[col + 1];
        #pragma unroll
        for (int mt = 0; mt < 4; mt++) {
            int r0 = m0 + wm + mt * 16 + g;
            int r1 = r0 + 8;
            float v0 = acc[mt][nt][0] + b0, v1 = acc[mt][nt][1] + b1;
            float v2 = acc[mt][nt][2] + b0, v3 = acc[mt][nt][3] + b1;
            if (EPI == 2) { v0 = gelu_f(v0); v1 = gelu_f(v1); v2 = gelu_f(v2); v3 = gelu_f(v3); }
            if (EPI == 1) {
                const float2 ra = *(const float2*)&res[(size_t)r0 * Nd + col];
                const float2 rb = *(const float2*)&res[(size_t)r1 * Nd + col];
                v0 += ra.x; v1 += ra.y; v2 += rb.x; v3 += rb.y;
            }
            store2(C, (size_t)r0 * Nd + col, v0, v1);
            store2(C, (size_t)r1 * Nd + col, v2, v3);
        }
    }
}

// ---------------------------------------------------------------------------
// Fused prologue (unchanged from R12)
// ---------------------------------------------------------------------------
__device__ __forceinline__ void transpose_blk(
    const float* __restrict__ S, __half* __restrict__ D,
    int R, int Ccol, int c0, int r0, int t)
{
    __shared__ float tl[32][33];
    int x = t & 31, y = t >> 5;
    #pragma unroll
    for (int j = 0; j < 32; j += 8)
        tl[y + j][x] = S[(size_t)(r0 + y + j) * Ccol + c0 + x];
    __syncthreads();
    #pragma unroll
    for (int j = 0; j < 32; j += 8)
        D[(size_t)(c0 + y + j) * R + r0 + x] = __float2half_rn(tl[x][y + j]);
}

#define PREP_CONV 8192
#define PREP_WX   (PREP_CONV)
#define PREP_WP   (PREP_WX + 256)
#define PREP_W1   (PREP_WP + 256)
#define PREP_W2   (PREP_W1 + 512)
#define PREP_TW1  (PREP_W2 + 512)
#define PREP_WSL  (PREP_TW1 + 4)
#define PREP_TOTAL (PREP_WSL + 4)

__global__ __launch_bounds__(256) void prep_k(
    const float* __restrict__ x,
    const float* __restrict__ Wx, const float* __restrict__ Wp,
    const float* __restrict__ W1, const float* __restrict__ W2,
    const float* __restrict__ tw1, const float* __restrict__ Wsl)
{
    const int id = blockIdx.x, t = threadIdx.x;
    if (id < PREP_CONV) {
        size_t i = ((size_t)id * 256 + t) * 8;
        float4 a = *(const float4*)&x[i];
        float4 b = *(const float4*)&x[i + 4];
        *(__half2*)&g_xh[i]     = __floats2half2_rn(a.x, a.y);
        *(__half2*)&g_xh[i + 2] = __floats2half2_rn(a.z, a.w);
        *(__half2*)&g_xh[i + 4] = __floats2half2_rn(b.x, b.y);
        *(__half2*)&g_xh[i + 6] = __floats2half2_rn(b.z, b.w);
    } else if (id < PREP_WP) {
        int i = id - PREP_WX;
        transpose_blk(Wx, g_bth + BT_WX, Dc, Dc, (i & 15) << 5, (i >> 4) << 5, t);
    } else if (id < PREP_W1) {
        int i = id - PREP_WP;
        transpose_blk(Wp, g_bth + BT_WP, Dc, Dc, (i & 15) << 5, (i >> 4) << 5, t);
    } else if (id < PREP_W2) {
        int i = id - PREP_W1;
        transpose_blk(W1, g_bth + BT_W1, Dc, HIDc, (i & 31) << 5, (i >> 5) << 5, t);
    } else if (id < PREP_TW1) {
        int i = id - PREP_W2;
        transpose_blk(W2, g_bth + BT_W2, HIDc, Dc, (i & 15) << 5, (i >> 4) << 5, t);
    } else if (id < PREP_WSL) {
        int i = id - PREP_TW1;
        transpose_blk(tw1, g_tw1T, 64, 64, (i & 1) << 5, (i >> 1) << 5, t);
    } else {
        int i = id - PREP_WSL;
        transpose_blk(Wsl, g_wslT, 64, 64, (i & 1) << 5, (i >> 1) << 5, t);
    }
}

// ---------------------------------------------------------------------------
// Router on tensor cores (unchanged from R12)
// ---------------------------------------------------------------------------
__global__ __launch_bounds__(256) void router_mma(
    const float* __restrict__ tb1, const float* __restrict__ tw2,
    const float* __restrict__ tb2, const float* __restrict__ bias,
    const float* __restrict__ bsl, const float* __restrict__ gumbel)
{
    __shared__ __half Xs[128*72];
    __shared__ __half W1s[64*72];
    __shared__ __half W2s[64*72];
    __shared__ float tb1s[64], tw2s[64], bsls[64];
    const int t = threadIdx.x, w = t >> 5, lane = t & 31;
    const int g = lane >> 2, q = lane & 3;
    const int m0 = blockIdx.x << 7;

    #pragma unroll
    for (int e = 0; e < 4; e++) {
        int sg = t + (e << 8);
        int r = sg >> 3, o = (sg & 7) << 3;
        cpa16(&Xs[r*72 + o], &g_xmh[(size_t)(m0 + r)*64 + o]);
    }
    #pragma unroll
    for (int e = 0; e < 2; e++) {
        int sg = t + (e << 8);
        int r = sg >> 3, o = (sg & 7) << 3;
        cpa16(&W1s[r*72 + o], &g_tw1T[r*64 + o]);
        cpa16(&W2s[r*72 + o], &g_wslT[r*64 + o]);
    }
    if (t < 64) { tb1s[t] = tb1[t]; tw2s[t] = tw2[t]; bsls[t] = bsl[t]; }
    CP_COMMIT(); CP_WAIT0();
    __syncthreads();

    unsigned af[4][4];
    #pragma unroll
    for (int ks = 0; ks < 4; ks++)
        ldsm4(af[ks], &Xs[(w*16 + (lane & 15))*72 + ks*16 + ((lane >> 4) << 3)]);

    float a1[8][4] = {}, a2[8][4] = {};
    #pragma unroll
    for (int nt = 0; nt < 8; nt++)
        #pragma unroll
        for (int ks = 0; ks < 4; ks++) {
            const __half* p1 = &W1s[(nt*8 + g)*72 + ks*16 + (q << 1)];
            const __half* p2 = &W2s[(nt*8 + g)*72 + ks*16 + (q << 1)];
            unsigned b1f[2] = {*(const unsigned*)p1, *(const unsigned*)(p1 + 8)};
            unsigned b2f[2] = {*(const unsigned*)p2, *(const unsigned*)(p2 + 8)};
            mma_f16(a1[nt], af[ks], b1f);
            mma_f16(a2[nt], af[ks], b2f);
        }

    const float tb2v = tb2[0];
    #pragma unroll
    for (int rr = 0; rr < 2; rr++) {
        const int m = m0 + w*16 + g + rr*8;
        const int h = m & 7;
        const int n = (m >> 3) & (Nc - 1);
        const int b = m >> 16;
        float p = 0.f;
        #pragma unroll
        for (int nt = 0; nt < 8; nt++) {
            int col = nt*8 + (q << 1);
            p += gelu_f(a1[nt][rr*2 + 0] + tb1s[col])     * tw2s[col];
            p += gelu_f(a1[nt][rr*2 + 1] + tb1s[col + 1]) * tw2s[col + 1];
        }
        p += __shfl_xor_sync(0xffffffffu, p, 1);
        p += __shfl_xor_sync(0xffffffffu, p, 2);
        const float invT = 1.0f / fmaxf(gelu_f(p + tb2v) + bias[h], 0.01f);

        const size_t gbase = (((size_t)b * Hc + h) * Nc + n) * 64;
        float z[8][2];
        float mx = -1e30f;
        #pragma unroll
        for (int nt = 0; nt < 8; nt++) {
            int col = nt*8 + (q << 1);
            float2 gu = *(const float2*)&gumbel[gbase + col];
            z[nt][0] = (a2[nt][rr*2 + 0] + bsls[col]     + gu.x) * invT;
            z[nt][1] = (a2[nt][rr*2 + 1] + bsls[col + 1] + gu.y) * invT;
            mx = fmaxf(mx, fmaxf(z[nt][0], z[nt][1]));
        }
        mx = fmaxf(mx, __shfl_xor_sync(0xffffffffu, mx, 1));
        mx = fmaxf(mx, __shfl_xor_sync(0xffffffffu, mx, 2));
        float sum = 0.f;
        #pragma unroll
        for (int nt = 0; nt < 8; nt++) {
            z[nt][0] = expf(z[nt][0] - mx);
            z[nt][1] = expf(z[nt][1] - mx);
            sum += z[nt][0] + z[nt][1];
        }
        sum += __shfl_xor_sync(0xffffffffu, sum, 1);
        sum += __shfl_xor_sync(0xffffffffu, sum, 2);
        const float inv = 1.0f / sum;
        #pragma unroll
        for (int nt = 0; nt < 8; nt++) {
            int col = nt*8 + (q << 1);
            *(__half2*)&g_swh[(size_t)m*64 + col] = __floats2half2_rn(z[nt][0]*inv, z[nt][1]*inv);
        }
    }
}

// ---------------------------------------------------------------------------
// Dispatch on tensor cores (unchanged from R12: SEGc=16, 8 chunks)
// ---------------------------------------------------------------------------
__global__ __launch_bounds__(256) void dispatch_mma()
{
    __shared__ __half swS[2][64*72];
    __shared__ __half xmS[2][64*72];
    const int t = threadIdx.x, w = t >> 5, lane = t & 31;
    const int g = lane >> 2, q = lane & 3;
    const int bh = blockIdx.x, s = blockIdx.y;
    const int b = bh >> 3, h = bh & 7;
    const int wm = (w & 3) << 4, wn = (w >> 2) << 5;
    const int lr = t >> 2;
    const int lo = (t & 3) << 4;
    const int trow = lane & 15;
    const int tcol = (lane >> 4) << 3;

    float acc[4][4] = {};
    float sn = 0.f;

    auto load_chunk = [&](int buf, int ch) {
        const int nb = s * SEGLEN + ch * 64;
        const size_t mrow = ((size_t)(b * Nc + nb + lr) * Hc + h) * 64;
        cpa16(&swS[buf][lr*72 + lo],     &g_swh[mrow + lo]);
        cpa16(&swS[buf][lr*72 + lo + 8], &g_swh[mrow + lo + 8]);
        cpa16(&xmS[buf][lr*72 + lo],     &g_xmh[mrow + lo]);
        cpa16(&xmS[buf][lr*72 + lo + 8], &g_xmh[mrow + lo + 8]);
        CP_COMMIT();
    };

    load_chunk(0, 0);
    load_chunk(1, 1);

    for (int ch = 0; ch < 8; ch++) {
        if (ch + 1 < 8) { CP_WAIT1(); } else { CP_WAIT0(); }
        __syncthreads();
        const int buf = ch & 1;
        const __half* swp = swS[buf];
        const __half* xmp = xmS[buf];

        if (t < 64) {
            float lsn = 0.f;
            #pragma unroll 8
            for (int tok = 0; tok < 64; tok++)
                lsn += __half2float(swp[tok*72 + t]);
            sn += lsn;
        }
        #pragma unroll
        for (int ks = 0; ks < 4; ks++) {
            const int tb = ks << 4;
            unsigned ar[4];
            ldsm4t(ar, &swp[(tb + trow)*72 + wm + tcol]);
            const unsigned af[4] = {ar[0], ar[2], ar[1], ar[3]};
            #pragma unroll
            for (int np = 0; np < 2; np++) {
                unsigned br[4];
                ldsm4t(br, &xmp[(tb + trow)*72 + wn + np*16 + tcol]);
                mma_f16(acc[np*2],     af, br);
                mma_f16(acc[np*2 + 1], af, br + 2);
            }
        }
        __syncthreads();
        if (ch + 2 < 8) load_chunk(buf, ch + 2);
    }

    const int base = bh * SEGc + s;
    #pragma unroll
    for (int nb = 0; nb < 4; nb++) {
        int col = wn + nb*8 + (q << 1);
        *(float2*)&g_stp[(size_t)base*4096 + (wm + g)*64 + col]     = make_float2(acc[nb][0], acc[nb][1]);
        *(float2*)&g_stp[(size_t)base*4096 + (wm + g + 8)*64 + col] = make_float2(acc[nb][2], acc[nb][3]);
    }
    if (t < 64) g_snp[base*64 + t] = sn;
}

// ---------------------------------------------------------------------------
// Fused reduce + slice attention (unchanged from R12)
// ---------------------------------------------------------------------------
#define SA_R 68
#define SA_SMEM ((1+3+3+1)*64*SA_R*4)

__global__ __launch_bounds__(256) void slice_attn(
    const float* __restrict__ Wq, const float* __restrict__ Wk, const float* __restrict__ Wv)
{
    extern __shared__ float sm[];
    float* STt = sm;
    float* Wsm = STt + 64 * SA_R;
    float* Qt  = Wsm + 3 * 64 * SA_R;
    float* Kt  = Qt + 64 * SA_R;
    float* Vs  = Kt + 64 * SA_R;
    float* Pt  = Vs + 64 * SA_R;
    __shared__ float invsn[64];

    const int bh = blockIdx.x, t = threadIdx.x;
    const int tx = t & 15, ty = t >> 4;
    const int r4 = ty << 2, c4 = tx << 2;

    if (t < 64) {
        float v = 1e-5f;
        for (int s = 0; s < SEGc; s++) v += g_snp[(bh * SEGc + s) * 64 + t];
        invsn[t] = 1.0f / v;
    }
    const float* Wg[3] = {Wq, Wk, Wv};
    #pragma unroll
    for (int m = 0; m < 3; m++)
        #pragma unroll
        for (int e = 0; e < 4; e++) {
            int idx = (t + (e << 8)) << 2;
            int r = idx >> 6, c = idx & 63;
            float4 wv4 = *(const float4*)&Wg[m][idx];
            *(float4*)&Wsm[(m * 64 + r) * SA_R + c] = wv4;
        }
    __syncthreads();

    #pragma unroll
    for (int e = 0; e < 16; e++) {
        int idx = t + (e << 8);
        float v = 0.f;
        #pragma unroll
        for (int s = 0; s < SEGc; s++) v += g_stp[(size_t)(bh * SEGc + s) * 4096 + idx];
        int tok = idx >> 6, d = idx & 63;
        STt[d * SA_R + tok] = v * invsn[tok];
    }
    __syncthreads();

    {
        float aq[4][4] = {}, ak[4][4] = {}, av[4][4] = {};
        #pragma unroll 4
        for (int d = 0; d < 64; d++) {
            float4 a4 = *(const float4*)&STt[d * SA_R + r4];
            float4 wq4 = *(const float4*)&Wsm[(0 * 64 + d) * SA_R + c4];
            float4 wk4 = *(const float4*)&Wsm[(1 * 64 + d) * SA_R + c4];
            float4 wv4 = *(const float4*)&Wsm[(2 * 64 + d) * SA_R + c4];
            const float a[4] = {a4.x, a4.y, a4.z, a4.w};
            const float uq[4] = {wq4.x, wq4.y, wq4.z, wq4.w};
            const float uk[4] = {wk4.x, wk4.y, wk4.z, wk4.w};
            const float uv[4] = {wv4.x, wv4.y, wv4.z, wv4.w};
            #pragma unroll
            for (int i = 0; i < 4; i++)
                #pragma unroll
                for (int j = 0; j < 4; j++) {
                    aq[i][j] += a[i] * uq[j];
                    ak[i][j] += a[i] * uk[j];
                    av[i][j] += a[i] * uv[j];
                }
        }
        __syncthreads();
        #pragma unroll
        for (int i = 0; i < 4; i++)
            #pragma unroll
            for (int j = 0; j < 4; j++) {
                Qt[(c4 + j) * SA_R + r4 + i] = aq[i][j];
                Kt[(c4 + j) * SA_R + r4 + i] = ak[i][j];
                Vs[(r4 + i) * SA_R + c4 + j] = av[i][j];
            }
    }
    __syncthreads();

    {
        float sc[4][4] = {};
        #pragma unroll 4
        for (int d = 0; d < 64; d++) {
            float4 a4 = *(const float4*)&Qt[d * SA_R + r4];
            float4 b4 = *(const float4*)&Kt[d * SA_R + c4];
            const float a[4] = {a4.x, a4.y, a4.z, a4.w};
            const float b[4] = {b4.x, b4.y, b4.z, b4.w};
            #pragma unroll
            for (int i = 0; i < 4; i++)
                #pragma unroll
                for (int j = 0; j < 4; j++) sc[i][j] += a[i] * b[j];
        }
        __syncthreads();
        #pragma unroll
        for (int i = 0; i < 4; i++)
            #pragma unroll
            for (int j = 0; j < 4; j++)
                Pt[(c4 + j) * SA_R + r4 + i] = sc[i][j] * 0.125f;
    }
    __syncthreads();

    if (t < 64) {
        float mx = -1e30f;
        #pragma unroll 8
        for (int j = 0; j < 64; j++) mx = fmaxf(mx, Pt[j * SA_R + t]);
        float sum = 0.f;
        #pragma unroll 8
        for (int j = 0; j < 64; j++) {
            float ee = expf(Pt[j * SA_R + t] - mx);
            Pt[j * SA_R + t] = ee;
            sum += ee;
        }
        float inv = 1.f / sum;
        #pragma unroll 8
        for (int j = 0; j < 64; j++) Pt[j * SA_R + t] *= inv;
    }
    __syncthreads();

    {
        float oc[4][4] = {};
        #pragma unroll 4
        for (int j = 0; j < 64; j++) {
            float4 a4 = *(const float4*)&Pt[j * SA_R + r4];
            float4 b4 = *(const float4*)&Vs[j * SA_R + c4];
            const float a[4] = {a4.x, a4.y, a4.z, a4.w};
            const float b[4] = {b4.x, b4.y, b4.z, b4.w};
            #pragma unroll
            for (int i = 0; i < 4; i++)
                #pragma unroll
                for (int jj = 0; jj < 4; jj++) oc[i][jj] += a[i] * b[jj];
        }
        #pragma unroll
        for (int i = 0; i < 4; i++)
            #pragma unroll
            for (int j = 0; j < 4; j++)
                g_osth[(size_t)bh * 4096 + (c4 + j) * 64 + (r4 + i)] = __float2half_rn(oc[i][j]);
    }
}

// ---------------------------------------------------------------------------
// Scatter on tensor cores (unchanged from R12)
// ---------------------------------------------------------------------------
__global__ __launch_bounds__(256) void scatter_mma()
{
    __shared__ __half As[128*72];
    __shared__ __half Bs[64*72];
    const int t = threadIdx.x, w = t >> 5, lane = t & 31;
    const int g = lane >> 2, q = lane & 3;
    const int tile = blockIdx.x;
    const int h = tile & 7, nt128 = (tile >> 3) & 63, b = tile >> 9;
    const int bh = b * 8 + h, n0 = nt128 << 7;

    #pragma unroll
    for (int e = 0; e < 2; e++) {
        int sg = t + (e << 8);
        int r = sg >> 3, o = (sg & 7) << 3;
        cpa16(&Bs[r*72 + o], &g_osth[(size_t)bh * 4096 + r*64 + o]);
    }
    #pragma unroll
    for (int e = 0; e < 4; e++) {
        int sg = t + (e << 8);
        int r = sg >> 3, o = (sg & 7) << 3;
        cpa16(&As[r*72 + o], &g_swh[((size_t)(b * Nc + n0 + r) * Hc + h) * 64 + o]);
    }
    CP_COMMIT(); CP_WAIT0();
    __syncthreads();

    unsigned af[4][4];
    #pragma unroll
    for (int ks = 0; ks < 4; ks++)
        ldsm4(af[ks], &As[(w*16 + (lane & 15))*72 + ks*16 + ((lane >> 4) << 3)]);
    float acc[8][4] = {};
    #pragma unroll
    for (int nt = 0; nt < 8; nt++)
        #pragma unroll
        for (int ks = 0; ks < 4; ks++) {
            const __half* bp = &Bs[(nt*8 + g)*72 + ks*16 + (q << 1)];
            unsigned bf[2] = {*(const unsigned*)bp, *(const unsigned*)(bp + 8)};
            mma_f16(acc[nt], af[ks], bf);
        }
    #pragma unroll
    for (int nt = 0; nt < 8; nt++) {
        int col = nt*8 + (q << 1);
        int r0 = n0 + w*16 + g;
        *(__half2*)&g_yh[(size_t)(b * Nc + r0) * Dc + h*64 + col] =
            __floats2half2_rn(acc[nt][0], acc[nt][1]);
        *(__half2*)&g_yh[(size_t)(b * Nc + r0 + 8) * Dc + h*64 + col] =
            __floats2half2_rn(acc[nt][2], acc[nt][3]);
    }
}

// ---------------------------------------------------------------------------
// LayerNorm: reads fp16 g_o2h, writes fp16 g_lnh
// ---------------------------------------------------------------------------
__global__ __launch_bounds__(128) void ln_k(
    const float* __restrict__ gam, const float* __restrict__ bet)
{
    int row = blockIdx.x, t = threadIdx.x;
    const __half2 h0 = *(const __half2*)&g_o2h[(size_t)row * Dc + (t << 2)];
    const __half2 h1 = *(const __half2*)&g_o2h[(size_t)row * Dc + (t << 2) + 2];
    float2 f0 = __half22float2(h0), f1 = __half22float2(h1);
    float s = f0.x + f0.y + f1.x + f1.y;
    __shared__ float rs[4];
    #pragma unroll
    for (int off = 16; off; off >>= 1) s += __shfl_xor_sync(0xffffffffu, s, off);
    int w = t >> 5;
    if ((t & 31) == 0) rs[w] = s;
    __syncthreads();
    float mean = (rs[0] + rs[1] + rs[2] + rs[3]) * (1.f / 512.f);
    float dx = f0.x - mean, dy = f0.y - mean, dz = f1.x - mean, dw = f1.y - mean;
    float qv = dx*dx + dy*dy + dz*dz + dw*dw;
    #pragma unroll
    for (int off = 16; off; off >>= 1) qv += __shfl_xor_sync(0xffffffffu, qv, off);
    __syncthreads();
    if ((t & 31) == 0) rs[w] = qv;
    __syncthreads();
    float var = (rs[0] + rs[1] + rs[2] + rs[3]) * (1.f / 512.f);
    float inv = rsqrtf(var + 1e-5f);
    float4 gv = *(const float4*)&gam[t << 2];
    float4 bv = *(const float4*)&bet[t << 2];
    size_t base = (size_t)row * Dc + (t << 2);
    *(__half2*)&g_lnh[base]     = __floats2half2_rn(dx * inv * gv.x + bv.x, dy * inv * gv.y + bv.y);
    *(__half2*)&g_lnh[base + 2] = __floats2half2_rn(dz * inv * gv.z + bv.z, dw * inv * gv.w + bv.w);
}

// ---------------------------------------------------------------------------
extern "C" void kernel_launch(void* const* d_in, const int* in_sizes, int n_in,
                              void* d_out, int out_size)
{
    const float* x      = (const float*)d_in[0];
    const float* gumbel = (const float*)d_in[1];
    const float* Wx     = (const float*)d_in[2];
    const float* bx     = (const float*)d_in[3];
    const float* tw1    = (const float*)d_in[4];
    const float* tb1    = (const float*)d_in[5];
    const float* tw2    = (const float*)d_in[6];
    const float* tb2    = (const float*)d_in[7];
    const float* bias   = (const float*)d_in[8];
    const float* Wsl    = (const float*)d_in[9];
    const float* bsl    = (const float*)d_in[10];
    const float* Wq     = (const float*)d_in[11];
    const float* Wk     = (const float*)d_in[12];
    const float* Wv     = (const float*)d_in[13];
    const float* Wp     = (const float*)d_in[14];
    const float* bp     = (const float*)d_in[15];
    const float* ln2g   = (const float*)d_in[16];
    const float* ln2b   = (const float*)d_in[17];
    const float* W1     = (const float*)d_in[18];
    const float* b1     = (const float*)d_in[19];
    const float* W2     = (const float*)d_in[20];
    const float* b2     = (const float*)d_in[21];
    float* out = (float*)d_out;

    __half *xh, *xmh, *yh, *lnh, *midh, *bth, *o2h;
    cudaGetSymbolAddress((void**)&o2h,  g_o2h);
    cudaGetSymbolAddress((void**)&xh,   g_xh);
    cudaGetSymbolAddress((void**)&xmh,  g_xmh);
    cudaGetSymbolAddress((void**)&yh,   g_yh);
    cudaGetSymbolAddress((void**)&lnh,  g_lnh);
    cudaGetSymbolAddress((void**)&midh, g_midh);
    cudaGetSymbolAddress((void**)&bth,  g_bth);

    cudaFuncSetAttribute((const void*)gemm_h16<0,__half>, cudaFuncAttributeMaxDynamicSharedMemorySize, GEMM_SMEM);
    cudaFuncSetAttribute((const void*)gemm_h16<1,__half>, cudaFuncAttributeMaxDynamicSharedMemorySize, GEMM_SMEM);
    cudaFuncSetAttribute((const void*)gemm_h16<1,float>,  cudaFuncAttributeMaxDynamicSharedMemorySize, GEMM_SMEM);
    cudaFuncSetAttribute((const void*)gemm_h16<2,__half>, cudaFuncAttributeMaxDynamicSharedMemorySize, GEMM_SMEM);
    cudaFuncSetAttribute((const void*)slice_attn,         cudaFuncAttributeMaxDynamicSharedMemorySize, SA_SMEM);

    // 0. fused prologue
    prep_k<<<PREP_TOTAL, 256>>>(x, Wx, Wp, W1, W2, tw1, Wsl);

    // 1. xm = x @ Wx + bx  (fp16 out)
    gemm_h16<0,__half><<<dim3(Dc/128, Mrows/128), 256, GEMM_SMEM>>>(xh, bth + BT_WX, bx, nullptr, xmh, Dc, Dc);
    // 2. router -> g_swh
    router_mma<<<MH/128, 256>>>(tb1, tw2, tb2, bias, bsl, gumbel);
    // 3. dispatch
    dispatch_mma<<<dim3(Bc*Hc, SEGc), 256>>>();
    // 4. reduce + slice attention -> g_osth
    slice_attn<<<Bc*Hc, 256, SA_SMEM>>>(Wq, Wk, Wv);
    // 5. scatter -> g_yh
    scatter_mma<<<Bc*Hc*64, 256>>>();
    // 6. o2 = y @ Wp + bp + x  (fp16 out; o2 only feeds LN)
    gemm_h16<1,__half><<<dim3(Dc/128, Mrows/128), 256, GEMM_SMEM>>>(yh, bth + BT_WP, bp, x, o2h, Dc, Dc);
    // 7. layernorm (fp16 in/out)
    ln_k<<<Mrows, 128>>>(ln2g, ln2b);
    // 8. mid = gelu(ln @ W1 + b1)  (fp16 out)
    gemm_h16<2,__half><<<dim3(HIDc/128, Mrows/128), 256, GEMM_SMEM>>>(lnh, bth + BT_W1, b1, nullptr, midh, Dc, HIDc);
    // 9. out = mid @ W2 + b2 + x
    gemm_h16<1,float><<<dim3(Dc/128, Mrows/128), 256, GEMM_SMEM>>>(midh, bth + BT_W2, b2, x, out, HIDc, Dc);
}

// round 16
// speedup vs baseline: 1.0275x; 1.0063x over previous
#include <cuda_runtime.h>
#include <cuda_fp16.h>
#include <math.h>
#include <stdint.h>

// Problem constants
#define Bc   4
#define Nc   8192
#define Dc   512
#define Hc   8
#define DHc  64
#define Kc   64
#define HIDc 1024
#define Mrows (Bc*Nc)        // 32768
#define MH    (Mrows*Hc)     // 262144 token-heads
#define SEGc  16
#define SEGLEN (Nc/SEGc)     // 512

// Scratch (device globals; no allocation allowed)
__device__ float  g_stp [Bc*Hc*SEGc*Kc*DHc];
__device__ float  g_snp [Bc*Hc*SEGc*Kc];
// fp16 operands
__device__ __half g_o2h [(size_t)Mrows*Dc];     // o2 (LN input) fp16
__device__ __half g_xh  [(size_t)Mrows*Dc];
__device__ __half g_xmh [(size_t)Mrows*Dc];
__device__ __half g_swh [(size_t)MH*Kc];
__device__ __half g_osth[Bc*Hc*Kc*DHc];
__device__ __half g_yh  [(size_t)Mrows*Dc];
__device__ __half g_lnh [(size_t)Mrows*Dc];
__device__ __half g_midh[(size_t)Mrows*HIDc];
// transposed fp16 weights [N][K]
#define BT_WX 0
#define BT_WP 262144
#define BT_W1 524288
#define BT_W2 1048576
__device__ __half g_bth [1572864];
__device__ __half g_tw1T[64*64];
__device__ __half g_wslT[64*64];

__device__ __forceinline__ float gelu_f(float x) {
    return 0.5f * x * (1.0f + erff(0.70710678118654752440f * x));
}
__device__ __forceinline__ unsigned s2u(const void* p) {
    return (unsigned)__cvta_generic_to_shared(p);
}
__device__ __forceinline__ void cpa16(void* s, const void* g) {
    unsigned sa = s2u(s);
    asm volatile("cp.async.cg.shared.global [%0], [%1], 16;\n" :: "r"(sa), "l"(g));
}
#define CP_COMMIT() asm volatile("cp.async.commit_group;\n")
#define CP_WAIT2()  asm volatile("cp.async.wait_group 2;\n")
#define CP_WAIT1()  asm volatile("cp.async.wait_group 1;\n")
#define CP_WAIT0()  asm volatile("cp.async.wait_group 0;\n")

__device__ __forceinline__ void mma_f16(float* c, const unsigned* a, const unsigned* b) {
    asm volatile(
        "mma.sync.aligned.m16n8k16.row.col.f32.f16.f16.f32 "
        "{%0,%1,%2,%3}, {%4,%5,%6,%7}, {%8,%9}, {%0,%1,%2,%3};\n"
        : "+f"(c[0]), "+f"(c[1]), "+f"(c[2]), "+f"(c[3])
        : "r"(a[0]), "r"(a[1]), "r"(a[2]), "r"(a[3]), "r"(b[0]), "r"(b[1]));
}
__device__ __forceinline__ void ldsm4(unsigned* r, const __half* p) {
    unsigned a = s2u(p);
    asm volatile("ldmatrix.sync.aligned.m8n8.x4.shared.b16 {%0,%1,%2,%3}, [%4];\n"
        : "=r"(r[0]), "=r"(r[1]), "=r"(r[2]), "=r"(r[3]) : "r"(a));
}
__device__ __forceinline__ void ldsm4t(unsigned* r, const __half* p) {
    unsigned a = s2u(p);
    asm volatile("ldmatrix.sync.aligned.m8n8.x4.trans.shared.b16 {%0,%1,%2,%3}, [%4];\n"
        : "=r"(r[0]), "=r"(r[1]), "=r"(r[2]), "=r"(r[3]) : "r"(a));
}
__device__ __forceinline__ void ldsmB(unsigned* r, const __half* tile, int n0,
                                      int stride, int kb, int lane) {
    int row = n0 + (lane & 7) + ((lane >> 4) << 3);
    int ko  = kb + (((lane >> 3) & 1) << 3);
    ldsm4(r, tile + row * stride + ko);
}
__device__ __forceinline__ void store2(float* C, size_t idx, float v0, float v1) {
    *(float2*)&C[idx] = make_float2(v0, v1);
}
__device__ __forceinline__ void store2(__half* C, size_t idx, float v0, float v1) {
    *(__half2*)&C[idx] = __floats2half2_rn(v0, v1);
}
__device__ __forceinline__ float2 ldres2(const float* p)  { return *(const float2*)p; }
__device__ __forceinline__ float2 ldres2(const __half* p) { return __half22float2(*(const __half2*)p); }

// ---------------------------------------------------------------------------
// FP16 tensor-core GEMM — R12 form (BK=32, 3-stage, ldsmB). ResT templated.
// ---------------------------------------------------------------------------
#define BKh 32
#define HS  40
#define STAGEH (128*HS)
#define NSTh 3
#define GEMM_SMEM (NSTh*2*STAGEH*2)

template<int EPI, typename OutT, typename ResT>
__global__ __launch_bounds__(256, 2) void gemm_h16(
    const __half* __restrict__ A, const __half* __restrict__ Bt,
    const float* __restrict__ bias, const ResT* __restrict__ res,
    OutT* __restrict__ C, int Kd, int Nd)
{
    extern __shared__ __half smh[];
    const int t = threadIdx.x;
    const int warp = t >> 5, lane = t & 31;
    const int g = lane >> 2, q = lane & 3;
    const int wm = (warp >> 2) << 6;
    const int wn = (warp & 3) << 5;
    const int m0 = blockIdx.y << 7;
    const int n0 = blockIdx.x << 7;
    const int lrow = lane & 15;
    const int lkof = (lane >> 4) << 3;
    const int r128 = t >> 1;
    const int hoff = (t & 1) << 4;
    const __half* Ap = A  + (size_t)(m0 + r128) * Kd + hoff;
    const __half* Bp = Bt + (size_t)(n0 + r128) * Kd + hoff;
    float acc[4][4][4] = {};

    auto load_tile = [&](int buf, int k0) {
        __half* As = smh + buf * 2 * STAGEH;
        __half* Bs = As + STAGEH;
        cpa16(As + r128 * HS + hoff,     Ap + k0);
        cpa16(As + r128 * HS + hoff + 8, Ap + k0 + 8);
        cpa16(Bs + r128 * HS + hoff,     Bp + k0);
        cpa16(Bs + r128 * HS + hoff + 8, Bp + k0 + 8);
        CP_COMMIT();
    };

    const int nk = Kd / BKh;
    load_tile(0, 0);
    load_tile(1, BKh);

    for (int it = 0; it < nk; ++it) {
        if (it + 2 < nk)       { load_tile((it + 2) % NSTh, (it + 2) * BKh); CP_WAIT2(); }
        else if (it + 2 == nk) { CP_WAIT1(); }
        else                   { CP_WAIT0(); }
        __syncthreads();
        const __half* As = smh + (it % NSTh) * 2 * STAGEH;
        const __half* Bs = As + STAGEH;
        #pragma unroll
        for (int ks = 0; ks < 2; ks++) {
            const int kb = ks << 4;
            unsigned af[4][4];
            #pragma unroll
            for (int mt = 0; mt < 4; mt++)
                ldsm4(af[mt], As + (wm + mt * 16 + lrow) * HS + kb + lkof);
            #pragma unroll
            for (int np = 0; np < 2; np++) {
                unsigned br[4];
                ldsmB(br, Bs, wn + np * 16, HS, kb, lane);
                #pragma unroll
                for (int mt = 0; mt < 4; mt++) {
                    mma_f16(acc[mt][2*np],     af[mt], br);
                    mma_f16(acc[mt][2*np + 1], af[mt], br + 2);
                }
            }
        }
        __syncthreads();
    }

    #pragma unroll
    for (int nt = 0; nt < 4; nt++) {
        const int col = n0 + wn + nt * 8 + (q << 1);
        const float b0 = bias[col], b1 = bias[col + 1];
        #pragma unroll
        for (int mt = 0; mt < 4; mt++) {
            int r0 = m0 + wm + mt * 16 + g;
            int r1 = r0 + 8;
            float v0 = acc[mt][nt][0] + b0, v1 = acc[mt][nt][1] + b1;
            float v2 = acc[mt][nt][2] + b0, v3 = acc[mt][nt][3] + b1;
            if (EPI == 2) { v0 = gelu_f(v0); v1 = gelu_f(v1); v2 = gelu_f(v2); v3 = gelu_f(v3); }
            if (EPI == 1) {
                const float2 ra = ldres2(&res[(size_t)r0 * Nd + col]);
                const float2 rb = ldres2(&res[(size_t)r1 * Nd + col]);
                v0 += ra.x; v1 += ra.y; v2 += rb.x; v3 += rb.y;
            }
            store2(C, (size_t)r0 * Nd + col, v0, v1);
            store2(C, (size_t)r1 * Nd + col, v2, v3);
        }
    }
}

// ---------------------------------------------------------------------------
// Fused prologue (unchanged)
// ---------------------------------------------------------------------------
__device__ __forceinline__ void transpose_blk(
    const float* __restrict__ S, __half* __restrict__ D,
    int R, int Ccol, int c0, int r0, int t)
{
    __shared__ float tl[32][33];
    int x = t & 31, y = t >> 5;
    #pragma unroll
    for (int j = 0; j < 32; j += 8)
        tl[y + j][x] = S[(size_t)(r0 + y + j) * Ccol + c0 + x];
    __syncthreads();
    #pragma unroll
    for (int j = 0; j < 32; j += 8)
        D[(size_t)(c0 + y + j) * R + r0 + x] = __float2half_rn(tl[x][y + j]);
}

#define PREP_CONV 8192
#define PREP_WX   (PREP_CONV)
#define PREP_WP   (PREP_WX + 256)
#define PREP_W1   (PREP_WP + 256)
#define PREP_W2   (PREP_W1 + 512)
#define PREP_TW1  (PREP_W2 + 512)
#define PREP_WSL  (PREP_TW1 + 4)
#define PREP_TOTAL (PREP_WSL + 4)

__global__ __launch_bounds__(256) void prep_k(
    const float* __restrict__ x,
    const float* __restrict__ Wx, const float* __restrict__ Wp,
    const float* __restrict__ W1, const float* __restrict__ W2,
    const float* __restrict__ tw1, const float* __restrict__ Wsl)
{
    const int id = blockIdx.x, t = threadIdx.x;
    if (id < PREP_CONV) {
        size_t i = ((size_t)id * 256 + t) * 8;
        float4 a = *(const float4*)&x[i];
        float4 b = *(const float4*)&x[i + 4];
        *(__half2*)&g_xh[i]     = __floats2half2_rn(a.x, a.y);
        *(__half2*)&g_xh[i + 2] = __floats2half2_rn(a.z, a.w);
        *(__half2*)&g_xh[i + 4] = __floats2half2_rn(b.x, b.y);
        *(__half2*)&g_xh[i + 6] = __floats2half2_rn(b.z, b.w);
    } else if (id < PREP_WP) {
        int i = id - PREP_WX;
        transpose_blk(Wx, g_bth + BT_WX, Dc, Dc, (i & 15) << 5, (i >> 4) << 5, t);
    } else if (id < PREP_W1) {
        int i = id - PREP_WP;
        transpose_blk(Wp, g_bth + BT_WP, Dc, Dc, (i & 15) << 5, (i >> 4) << 5, t);
    } else if (id < PREP_W2) {
        int i = id - PREP_W1;
        transpose_blk(W1, g_bth + BT_W1, Dc, HIDc, (i & 31) << 5, (i >> 5) << 5, t);
    } else if (id < PREP_TW1) {
        int i = id - PREP_W2;
        transpose_blk(W2, g_bth + BT_W2, HIDc, Dc, (i & 15) << 5, (i >> 4) << 5, t);
    } else if (id < PREP_WSL) {
        int i = id - PREP_TW1;
        transpose_blk(tw1, g_tw1T, 64, 64, (i & 1) << 5, (i >> 1) << 5, t);
    } else {
        int i = id - PREP_WSL;
        transpose_blk(Wsl, g_wslT, 64, 64, (i & 1) << 5, (i >> 1) << 5, t);
    }
}

// ---------------------------------------------------------------------------
// Router on tensor cores (unchanged)
// ---------------------------------------------------------------------------
__global__ __launch_bounds__(256) void router_mma(
    const float* __restrict__ tb1, const float* __restrict__ tw2,
    const float* __restrict__ tb2, const float* __restrict__ bias,
    const float* __restrict__ bsl, const float* __restrict__ gumbel)
{
    __shared__ __half Xs[128*72];
    __shared__ __half W1s[64*72];
    __shared__ __half W2s[64*72];
    __shared__ float tb1s[64], tw2s[64], bsls[64];
    const int t = threadIdx.x, w = t >> 5, lane = t & 31;
    const int g = lane >> 2, q = lane & 3;
    const int m0 = blockIdx.x << 7;

    #pragma unroll
    for (int e = 0; e < 4; e++) {
        int sg = t + (e << 8);
        int r = sg >> 3, o = (sg & 7) << 3;
        cpa16(&Xs[r*72 + o], &g_xmh[(size_t)(m0 + r)*64 + o]);
    }
    #pragma unroll
    for (int e = 0; e < 2; e++) {
        int sg = t + (e << 8);
        int r = sg >> 3, o = (sg & 7) << 3;
        cpa16(&W1s[r*72 + o], &g_tw1T[r*64 + o]);
        cpa16(&W2s[r*72 + o], &g_wslT[r*64 + o]);
    }
    if (t < 64) { tb1s[t] = tb1[t]; tw2s[t] = tw2[t]; bsls[t] = bsl[t]; }
    CP_COMMIT(); CP_WAIT0();
    __syncthreads();

    unsigned af[4][4];
    #pragma unroll
    for (int ks = 0; ks < 4; ks++)
        ldsm4(af[ks], &Xs[(w*16 + (lane & 15))*72 + ks*16 + ((lane >> 4) << 3)]);

    float a1[8][4] = {}, a2[8][4] = {};
    #pragma unroll
    for (int nt = 0; nt < 8; nt++)
        #pragma unroll
        for (int ks = 0; ks < 4; ks++) {
            const __half* p1 = &W1s[(nt*8 + g)*72 + ks*16 + (q << 1)];
            const __half* p2 = &W2s[(nt*8 + g)*72 + ks*16 + (q << 1)];
            unsigned b1f[2] = {*(const unsigned*)p1, *(const unsigned*)(p1 + 8)};
            unsigned b2f[2] = {*(const unsigned*)p2, *(const unsigned*)(p2 + 8)};
            mma_f16(a1[nt], af[ks], b1f);
            mma_f16(a2[nt], af[ks], b2f);
        }

    const float tb2v = tb2[0];
    #pragma unroll
    for (int rr = 0; rr < 2; rr++) {
        const int m = m0 + w*16 + g + rr*8;
        const int h = m & 7;
        const int n = (m >> 3) & (Nc - 1);
        const int b = m >> 16;
        float p = 0.f;
        #pragma unroll
        for (int nt = 0; nt < 8; nt++) {
            int col = nt*8 + (q << 1);
            p += gelu_f(a1[nt][rr*2 + 0] + tb1s[col])     * tw2s[col];
            p += gelu_f(a1[nt][rr*2 + 1] + tb1s[col + 1]) * tw2s[col + 1];
        }
        p += __shfl_xor_sync(0xffffffffu, p, 1);
        p += __shfl_xor_sync(0xffffffffu, p, 2);
        const float invT = 1.0f / fmaxf(gelu_f(p + tb2v) + bias[h], 0.01f);

        const size_t gbase = (((size_t)b * Hc + h) * Nc + n) * 64;
        float z[8][2];
        float mx = -1e30f;
        #pragma unroll
        for (int nt = 0; nt < 8; nt++) {
            int col = nt*8 + (q << 1);
            float2 gu = *(const float2*)&gumbel[gbase + col];
            z[nt][0] = (a2[nt][rr*2 + 0] + bsls[col]     + gu.x) * invT;
            z[nt][1] = (a2[nt][rr*2 + 1] + bsls[col + 1] + gu.y) * invT;
            mx = fmaxf(mx, fmaxf(z[nt][0], z[nt][1]));
        }
        mx = fmaxf(mx, __shfl_xor_sync(0xffffffffu, mx, 1));
        mx = fmaxf(mx, __shfl_xor_sync(0xffffffffu, mx, 2));
        float sum = 0.f;
        #pragma unroll
        for (int nt = 0; nt < 8; nt++) {
            z[nt][0] = expf(z[nt][0] - mx);
            z[nt][1] = expf(z[nt][1] - mx);
            sum += z[nt][0] + z[nt][1];
        }
        sum += __shfl_xor_sync(0xffffffffu, sum, 1);
        sum += __shfl_xor_sync(0xffffffffu, sum, 2);
        const float inv = 1.0f / sum;
        #pragma unroll
        for (int nt = 0; nt < 8; nt++) {
            int col = nt*8 + (q << 1);
            *(__half2*)&g_swh[(size_t)m*64 + col] = __floats2half2_rn(z[nt][0]*inv, z[nt][1]*inv);
        }
    }
}

// ---------------------------------------------------------------------------
// Dispatch on tensor cores (unchanged)
// ---------------------------------------------------------------------------
__global__ __launch_bounds__(256) void dispatch_mma()
{
    __shared__ __half swS[2][64*72];
    __shared__ __half xmS[2][64*72];
    const int t = threadIdx.x, w = t >> 5, lane = t & 31;
    const int g = lane >> 2, q = lane & 3;
    const int bh = blockIdx.x, s = blockIdx.y;
    const int b = bh >> 3, h = bh & 7;
    const int wm = (w & 3) << 4, wn = (w >> 2) << 5;
    const int lr = t >> 2;
    const int lo = (t & 3) << 4;
    const int trow = lane & 15;
    const int tcol = (lane >> 4) << 3;

    float acc[4][4] = {};
    float sn = 0.f;

    auto load_chunk = [&](int buf, int ch) {
        const int nb = s * SEGLEN + ch * 64;
        const size_t mrow = ((size_t)(b * Nc + nb + lr) * Hc + h) * 64;
        cpa16(&swS[buf][lr*72 + lo],     &g_swh[mrow + lo]);
        cpa16(&swS[buf][lr*72 + lo + 8], &g_swh[mrow + lo + 8]);
        cpa16(&xmS[buf][lr*72 + lo],     &g_xmh[mrow + lo]);
        cpa16(&xmS[buf][lr*72 + lo + 8], &g_xmh[mrow + lo + 8]);
        CP_COMMIT();
    };

    load_chunk(0, 0);
    load_chunk(1, 1);

    for (int ch = 0; ch < 8; ch++) {
        if (ch + 1 < 8) { CP_WAIT1(); } else { CP_WAIT0(); }
        __syncthreads();
        const int buf = ch & 1;
        const __half* swp = swS[buf];
        const __half* xmp = xmS[buf];

        if (t < 64) {
            float lsn = 0.f;
            #pragma unroll 8
            for (int tok = 0; tok < 64; tok++)
                lsn += __half2float(swp[tok*72 + t]);
            sn += lsn;
        }
        #pragma unroll
        for (int ks = 0; ks < 4; ks++) {
            const int tb = ks << 4;
            unsigned ar[4];
            ldsm4t(ar, &swp[(tb + trow)*72 + wm + tcol]);
            const unsigned af[4] = {ar[0], ar[2], ar[1], ar[3]};
            #pragma unroll
            for (int np = 0; np < 2; np++) {
                unsigned br[4];
                ldsm4t(br, &xmp[(tb + trow)*72 + wn + np*16 + tcol]);
                mma_f16(acc[np*2],     af, br);
                mma_f16(acc[np*2 + 1], af, br + 2);
            }
        }
        __syncthreads();
        if (ch + 2 < 8) load_chunk(buf, ch + 2);
    }

    const int base = bh * SEGc + s;
    #pragma unroll
    for (int nb = 0; nb < 4; nb++) {
        int col = wn + nb*8 + (q << 1);
        *(float2*)&g_stp[(size_t)base*4096 + (wm + g)*64 + col]     = make_float2(acc[nb][0], acc[nb][1]);
        *(float2*)&g_stp[(size_t)base*4096 + (wm + g + 8)*64 + col] = make_float2(acc[nb][2], acc[nb][3]);
    }
    if (t < 64) g_snp[base*64 + t] = sn;
}

// ---------------------------------------------------------------------------
// Fused reduce + slice attention (unchanged)
// ---------------------------------------------------------------------------
#define SA_R 68
#define SA_SMEM ((1+3+3+1)*64*SA_R*4)

__global__ __launch_bounds__(256) void slice_attn(
    const float* __restrict__ Wq, const float* __restrict__ Wk, const float* __restrict__ Wv)
{
    extern __shared__ float sm[];
    float* STt = sm;
    float* Wsm = STt + 64 * SA_R;
    float* Qt  = Wsm + 3 * 64 * SA_R;
    float* Kt  = Qt + 64 * SA_R;
    float* Vs  = Kt + 64 * SA_R;
    float* Pt  = Vs + 64 * SA_R;
    __shared__ float invsn[64];

    const int bh = blockIdx.x, t = threadIdx.x;
    const int tx = t & 15, ty = t >> 4;
    const int r4 = ty << 2, c4 = tx << 2;

    if (t < 64) {
        float v = 1e-5f;
        for (int s = 0; s < SEGc; s++) v += g_snp[(bh * SEGc + s) * 64 + t];
        invsn[t] = 1.0f / v;
    }
    const float* Wg[3] = {Wq, Wk, Wv};
    #pragma unroll
    for (int m = 0; m < 3; m++)
        #pragma unroll
        for (int e = 0; e < 4; e++) {
            int idx = (t + (e << 8)) << 2;
            int r = idx >> 6, c = idx & 63;
            float4 wv4 = *(const float4*)&Wg[m][idx];
            *(float4*)&Wsm[(m * 64 + r) * SA_R + c] = wv4;
        }
    __syncthreads();

    #pragma unroll
    for (int e = 0; e < 16; e++) {
        int idx = t + (e << 8);
        float v = 0.f;
        #pragma unroll
        for (int s = 0; s < SEGc; s++) v += g_stp[(size_t)(bh * SEGc + s) * 4096 + idx];
        int tok = idx >> 6, d = idx & 63;
        STt[d * SA_R + tok] = v * invsn[tok];
    }
    __syncthreads();

    {
        float aq[4][4] = {}, ak[4][4] = {}, av[4][4] = {};
        #pragma unroll 4
        for (int d = 0; d < 64; d++) {
            float4 a4 = *(const float4*)&STt[d * SA_R + r4];
            float4 wq4 = *(const float4*)&Wsm[(0 * 64 + d) * SA_R + c4];
            float4 wk4 = *(const float4*)&Wsm[(1 * 64 + d) * SA_R + c4];
            float4 wv4 = *(const float4*)&Wsm[(2 * 64 + d) * SA_R + c4];
            const float a[4] = {a4.x, a4.y, a4.z, a4.w};
            const float uq[4] = {wq4.x, wq4.y, wq4.z, wq4.w};
            const float uk[4] = {wk4.x, wk4.y, wk4.z, wk4.w};
            const float uv[4] = {wv4.x, wv4.y, wv4.z, wv4.w};
            #pragma unroll
            for (int i = 0; i < 4; i++)
                #pragma unroll
                for (int j = 0; j < 4; j++) {
                    aq[i][j] += a[i] * uq[j];
                    ak[i][j] += a[i] * uk[j];
                    av[i][j] += a[i] * uv[j];
                }
        }
        __syncthreads();
        #pragma unroll
        for (int i = 0; i < 4; i++)
            #pragma unroll
            for (int j = 0; j < 4; j++) {
                Qt[(c4 + j) * SA_R + r4 + i] = aq[i][j];
                Kt[(c4 + j) * SA_R + r4 + i] = ak[i][j];
                Vs[(r4 + i) * SA_R + c4 + j] = av[i][j];
            }
    }
    __syncthreads();

    {
        float sc[4][4] = {};
        #pragma unroll 4
        for (int d = 0; d < 64; d++) {
            float4 a4 = *(const float4*)&Qt[d * SA_R + r4];
            float4 b4 = *(const float4*)&Kt[d * SA_R + c4];
            const float a[4] = {a4.x, a4.y, a4.z, a4.w};
            const float b[4] = {b4.x, b4.y, b4.z, b4.w};
            #pragma unroll
            for (int i = 0; i < 4; i++)
                #pragma unroll
                for (int j = 0; j < 4; j++) sc[i][j] += a[i] * b[j];
        }
        __syncthreads();
        #pragma unroll
        for (int i = 0; i < 4; i++)
            #pragma unroll
            for (int j = 0; j < 4; j++)
                Pt[(c4 + j) * SA_R + r4 + i] = sc[i][j] * 0.125f;
    }
    __syncthreads();

    if (t < 64) {
        float mx = -1e30f;
        #pragma unroll 8
        for (int j = 0; j < 64; j++) mx = fmaxf(mx, Pt[j * SA_R + t]);
        float sum = 0.f;
        #pragma unroll 8
        for (int j = 0; j < 64; j++) {
            float ee = expf(Pt[j * SA_R + t] - mx);
            Pt[j * SA_R + t] = ee;
            sum += ee;
        }
        float inv = 1.f / sum;
        #pragma unroll 8
        for (int j = 0; j < 64; j++) Pt[j * SA_R + t] *= inv;
    }
    __syncthreads();

    {
        float oc[4][4] = {};
        #pragma unroll 4
        for (int j = 0; j < 64; j++) {
            float4 a4 = *(const float4*)&Pt[j * SA_R + r4];
            float4 b4 = *(const float4*)&Vs[j * SA_R + c4];
            const float a[4] = {a4.x, a4.y, a4.z, a4.w};
            const float b[4] = {b4.x, b4.y, b4.z, b4.w};
            #pragma unroll
            for (int i = 0; i < 4; i++)
                #pragma unroll
                for (int jj = 0; jj < 4; jj++) oc[i][jj] += a[i] * b[jj];
        }
        #pragma unroll
        for (int i = 0; i < 4; i++)
            #pragma unroll
            for (int j = 0; j < 4; j++)
                g_osth[(size_t)bh * 4096 + (c4 + j) * 64 + (r4 + i)] = __float2half_rn(oc[i][j]);
    }
}

// ---------------------------------------------------------------------------
// Scatter on tensor cores (unchanged)
// ---------------------------------------------------------------------------
__global__ __launch_bounds__(256) void scatter_mma()
{
    __shared__ __half As[128*72];
    __shared__ __half Bs[64*72];
    const int t = threadIdx.x, w = t >> 5, lane = t & 31;
    const int g = lane >> 2, q = lane & 3;
    const int tile = blockIdx.x;
    const int h = tile & 7, nt128 = (tile >> 3) & 63, b = tile >> 9;
    const int bh = b * 8 + h, n0 = nt128 << 7;

    #pragma unroll
    for (int e = 0; e < 2; e++) {
        int sg = t + (e << 8);
        int r = sg >> 3, o = (sg & 7) << 3;
        cpa16(&Bs[r*72 + o], &g_osth[(size_t)bh * 4096 + r*64 + o]);
    }
    #pragma unroll
    for (int e = 0; e < 4; e++) {
        int sg = t + (e << 8);
        int r = sg >> 3, o = (sg & 7) << 3;
        cpa16(&As[r*72 + o], &g_swh[((size_t)(b * Nc + n0 + r) * Hc + h) * 64 + o]);
    }
    CP_COMMIT(); CP_WAIT0();
    __syncthreads();

    unsigned af[4][4];
    #pragma unroll
    for (int ks = 0; ks < 4; ks++)
        ldsm4(af[ks], &As[(w*16 + (lane & 15))*72 + ks*16 + ((lane >> 4) << 3)]);
    float acc[8][4] = {};
    #pragma unroll
    for (int nt = 0; nt < 8; nt++)
        #pragma unroll
        for (int ks = 0; ks < 4; ks++) {
            const __half* bp = &Bs[(nt*8 + g)*72 + ks*16 + (q << 1)];
            unsigned bf[2] = {*(const unsigned*)bp, *(const unsigned*)(bp + 8)};
            mma_f16(acc[nt], af[ks], bf);
        }
    #pragma unroll
    for (int nt = 0; nt < 8; nt++) {
        int col = nt*8 + (q << 1);
        int r0 = n0 + w*16 + g;
        *(__half2*)&g_yh[(size_t)(b * Nc + r0) * Dc + h*64 + col] =
            __floats2half2_rn(acc[nt][0], acc[nt][1]);
        *(__half2*)&g_yh[(size_t)(b * Nc + r0 + 8) * Dc + h*64 + col] =
            __floats2half2_rn(acc[nt][2], acc[nt][3]);
    }
}

// ---------------------------------------------------------------------------
// LayerNorm: reads fp16 g_o2h, writes fp16 g_lnh (unchanged from R15)
// ---------------------------------------------------------------------------
__global__ __launch_bounds__(128) void ln_k(
    const float* __restrict__ gam, const float* __restrict__ bet)
{
    int row = blockIdx.x, t = threadIdx.x;
    const __half2 h0 = *(const __half2*)&g_o2h[(size_t)row * Dc + (t << 2)];
    const __half2 h1 = *(const __half2*)&g_o2h[(size_t)row * Dc + (t << 2) + 2];
    float2 f0 = __half22float2(h0), f1 = __half22float2(h1);
    float s = f0.x + f0.y + f1.x + f1.y;
    __shared__ float rs[4];
    #pragma unroll
    for (int off = 16; off; off >>= 1) s += __shfl_xor_sync(0xffffffffu, s, off);
    int w = t >> 5;
    if ((t & 31) == 0) rs[w] = s;
    __syncthreads();
    float mean = (rs[0] + rs[1] + rs[2] + rs[3]) * (1.f / 512.f);
    float dx = f0.x - mean, dy = f0.y - mean, dz = f1.x - mean, dw = f1.y - mean;
    float qv = dx*dx + dy*dy + dz*dz + dw*dw;
    #pragma unroll
    for (int off = 16; off; off >>= 1) qv += __shfl_xor_sync(0xffffffffu, qv, off);
    __syncthreads();
    if ((t & 31) == 0) rs[w] = qv;
    __syncthreads();
    float var = (rs[0] + rs[1] + rs[2] + rs[3]) * (1.f / 512.f);
    float inv = rsqrtf(var + 1e-5f);
    float4 gv = *(const float4*)&gam[t << 2];
    float4 bv = *(const float4*)&bet[t << 2];
    size_t base = (size_t)row * Dc + (t << 2);
    *(__half2*)&g_lnh[base]     = __floats2half2_rn(dx * inv * gv.x + bv.x, dy * inv * gv.y + bv.y);
    *(__half2*)&g_lnh[base + 2] = __floats2half2_rn(dz * inv * gv.z + bv.z, dw * inv * gv.w + bv.w);
}

// ---------------------------------------------------------------------------
extern "C" void kernel_launch(void* const* d_in, const int* in_sizes, int n_in,
                              void* d_out, int out_size)
{
    const float* x      = (const float*)d_in[0];
    const float* gumbel = (const float*)d_in[1];
    const float* Wx     = (const float*)d_in[2];
    const float* bx     = (const float*)d_in[3];
    const float* tw1    = (const float*)d_in[4];
    const float* tb1    = (const float*)d_in[5];
    const float* tw2    = (const float*)d_in[6];
    const float* tb2    = (const float*)d_in[7];
    const float* bias   = (const float*)d_in[8];
    const float* Wsl    = (const float*)d_in[9];
    const float* bsl    = (const float*)d_in[10];
    const float* Wq     = (const float*)d_in[11];
    const float* Wk     = (const float*)d_in[12];
    const float* Wv     = (const float*)d_in[13];
    const float* Wp     = (const float*)d_in[14];
    const float* bp     = (const float*)d_in[15];
    const float* ln2g   = (const float*)d_in[16];
    const float* ln2b   = (const float*)d_in[17];
    const float* W1     = (const float*)d_in[18];
    const float* b1     = (const float*)d_in[19];
    const float* W2     = (const float*)d_in[20];
    const float* b2     = (const float*)d_in[21];
    float* out = (float*)d_out;

    __half *xh, *xmh, *yh, *lnh, *midh, *bth, *o2h;
    cudaGetSymbolAddress((void**)&o2h,  g_o2h);
    cudaGetSymbolAddress((void**)&xh,   g_xh);
    cudaGetSymbolAddress((void**)&xmh,  g_xmh);
    cudaGetSymbolAddress((void**)&yh,   g_yh);
    cudaGetSymbolAddress((void**)&lnh,  g_lnh);
    cudaGetSymbolAddress((void**)&midh, g_midh);
    cudaGetSymbolAddress((void**)&bth,  g_bth);

    cudaFuncSetAttribute((const void*)gemm_h16<0,__half,float>,  cudaFuncAttributeMaxDynamicSharedMemorySize, GEMM_SMEM);
    cudaFuncSetAttribute((const void*)gemm_h16<1,__half,__half>, cudaFuncAttributeMaxDynamicSharedMemorySize, GEMM_SMEM);
    cudaFuncSetAttribute((const void*)gemm_h16<1,float,float>,   cudaFuncAttributeMaxDynamicSharedMemorySize, GEMM_SMEM);
    cudaFuncSetAttribute((const void*)gemm_h16<2,__half,float>,  cudaFuncAttributeMaxDynamicSharedMemorySize, GEMM_SMEM);
    cudaFuncSetAttribute((const void*)slice_attn,                cudaFuncAttributeMaxDynamicSharedMemorySize, SA_SMEM);

    // 0. fused prologue
    prep_k<<<PREP_TOTAL, 256>>>(x, Wx, Wp, W1, W2, tw1, Wsl);

    // 1. xm = x @ Wx + bx  (fp16 out)
    gemm_h16<0,__half,float><<<dim3(Dc/128, Mrows/128), 256, GEMM_SMEM>>>(xh, bth + BT_WX, bx, nullptr, xmh, Dc, Dc);
    // 2. router -> g_swh
    router_mma<<<MH/128, 256>>>(tb1, tw2, tb2, bias, bsl, gumbel);
    // 3. dispatch
    dispatch_mma<<<dim3(Bc*Hc, SEGc), 256>>>();
    // 4. reduce + slice attention -> g_osth
    slice_attn<<<Bc*Hc, 256, SA_SMEM>>>(Wq, Wk, Wv);
    // 5. scatter -> g_yh
    scatter_mma<<<Bc*Hc*64, 256>>>();
    // 6. o2 = y @ Wp + bp + x  (fp16 out, fp16 residual — o2 already fp16-rounded)
    gemm_h16<1,__half,__half><<<dim3(Dc/128, Mrows/128), 256, GEMM_SMEM>>>(yh, bth + BT_WP, bp, xh, o2h, Dc, Dc);
    // 7. layernorm (fp16 in/out)
    ln_k<<<Mrows, 128>>>(ln2g, ln2b);
    // 8. mid = gelu(ln @ W1 + b1)  (fp16 out)
    gemm_h16<2,__half,float><<<dim3(HIDc/128, Mrows/128), 256, GEMM_SMEM>>>(lnh, bth + BT_W1, b1, nullptr, midh, Dc, HIDc);
    // 9. out = mid @ W2 + b2 + x  (fp32 residual — final output precision)
    gemm_h16<1,float,float><<<dim3(Dc/128, Mrows/128), 256, GEMM_SMEM>>>(midh, bth + BT_W2, b2, x, out, HIDc, Dc);
}